// round 14
// baseline (speedup 1.0000x reference)
#include <cuda_runtime.h>
#include <cuda_fp16.h>
#include <math.h>
#include <stdint.h>

#define BB 16
#define SS 1025
#define HH 384
#define NHH 6
#define LL 12
#define II 1536
#define NCC 1000
#define MTOK (BB*SS)       // 16400
#define NPATCH 1024
#define MPATCH (BB*NPATCH) // 16384
#define QKVN 1152          // 3*HH
#define PK 768             // patch K = 3*16*16

// ---------------- scratch (__device__ globals; allocation-free rule) -------
__device__ __align__(256) __half g_h[MTOK*HH];          // fp16 residual stream
__device__ __align__(256) __half g_hn[MTOK*HH];
__device__ __align__(256) __half g_qkv[(size_t)MTOK*QKVN];
__device__ __align__(256) __half g_attn[MTOK*HH];
__device__ __align__(256) __half g_mlp[MTOK*II];
__device__ __align__(256) __half g_xh[(size_t)BB*3*512*512];
__device__ __align__(256) __half g_cwh[HH*PK];
// fp16 weights, pre-transposed to [L][N][K]
__device__ __align__(256) __half g_wqkv[(size_t)LL*QKVN*HH];
__device__ __align__(256) float  g_bqkv[LL*QKVN];
__device__ __align__(256) __half g_wot[LL*HH*HH];
__device__ __align__(256) __half g_w1t[(size_t)LL*II*HH];
__device__ __align__(256) __half g_w2t[(size_t)LL*HH*II];

// ---------------------------- helpers ---------------------------------------
__device__ __forceinline__ uint32_t smem_u32(const void* p) {
    uint32_t a;
    asm("{ .reg .u64 t; cvta.to.shared.u64 t, %1; cvt.u32.u64 %0, t; }"
        : "=r"(a) : "l"(p));
    return a;
}

__device__ __forceinline__ void cp16(uint32_t dst, const void* src, int nbytes) {
    asm volatile("cp.async.cg.shared.global [%0], [%1], 16, %2;"
                 :: "r"(dst), "l"(src), "r"(nbytes) : "memory");
}
#define CP_COMMIT asm volatile("cp.async.commit_group;" ::: "memory")
#define CP_WAIT0  asm volatile("cp.async.wait_group 0;" ::: "memory")
#define CP_WAIT1  asm volatile("cp.async.wait_group 1;" ::: "memory")

__device__ __forceinline__ void mma16(float* c, const uint32_t* a,
                                      uint32_t b0, uint32_t b1) {
    asm volatile("mma.sync.aligned.m16n8k16.row.col.f32.f16.f16.f32 "
        "{%0,%1,%2,%3}, {%4,%5,%6,%7}, {%8,%9}, {%0,%1,%2,%3};"
        : "+f"(c[0]), "+f"(c[1]), "+f"(c[2]), "+f"(c[3])
        : "r"(a[0]), "r"(a[1]), "r"(a[2]), "r"(a[3]), "r"(b0), "r"(b1));
}

__device__ __forceinline__ void ldmx4(uint32_t& r0, uint32_t& r1,
                                      uint32_t& r2, uint32_t& r3, uint32_t addr) {
    asm volatile("ldmatrix.sync.aligned.m8n8.x4.shared.b16 {%0,%1,%2,%3}, [%4];"
        : "=r"(r0), "=r"(r1), "=r"(r2), "=r"(r3) : "r"(addr));
}

__device__ __forceinline__ void ldmx4t(uint32_t& r0, uint32_t& r1,
                                       uint32_t& r2, uint32_t& r3, uint32_t addr) {
    asm volatile("ldmatrix.sync.aligned.m8n8.x4.trans.shared.b16 {%0,%1,%2,%3}, [%4];"
        : "=r"(r0), "=r"(r1), "=r"(r2), "=r"(r3) : "r"(addr));
}

__device__ __forceinline__ void ldmx2t(uint32_t& r0, uint32_t& r1, uint32_t addr) {
    asm volatile("ldmatrix.sync.aligned.m8n8.x2.trans.shared.b16 {%0,%1}, [%2];"
        : "=r"(r0), "=r"(r1) : "r"(addr));
}

__device__ __forceinline__ uint32_t h2ex2(uint32_t x) {
    uint32_t r;
    asm("ex2.approx.f16x2 %0, %1;" : "=r"(r) : "r"(x));
    return r;
}

__device__ __forceinline__ float gelu_f(float u) {
    float a = -1.5957691216057308f * (u + 0.044715f * u * u * u);
    float e = __expf(fminf(a, 80.0f));
    float th = (1.0f - e) / (1.0f + e);
    return 0.5f * u * (1.0f + th);
}

// ------------------------- dense mma GEMM (fp16) -----------------------------
// C[M,N] = A[M,K] @ W^T (W stored [N][K]) + bias. All outputs fp16.
// EPI 0: bias; 1: bias + residual (C += old, fp32 math); 2: bias + gelu
// Block 128x128, 256 thr (8 warps: 4m x 2n), warp 32x64, K-chunk 64, 3 stages.
#define DG_SMEM (6*9216*2)

template <int EPI>
__global__ void __launch_bounds__(256)
mma_gemm(const __half* __restrict__ A, const __half* __restrict__ Bw,
         const float* __restrict__ bias, __half* __restrict__ C,
         int M, int N, int K)
{
    extern __shared__ __align__(16) __half smh[];
    uint32_t sbase = smem_u32(smh);
    int tid = threadIdx.x, lane = tid & 31, w = tid >> 5;
    int gid = lane >> 2, tig = lane & 3;
    int wm0 = (w & 3) * 32, wn0 = (w >> 2) * 64;
    int m0 = blockIdx.y * 128, n0 = blockIdx.x * 128;
    int l8 = lane & 7;
    int aRowOff = ((lane >> 3) & 1) * 8 + l8, aColOff = (lane >> 4) * 8;
    int bRowOff = (lane >> 4) * 8 + l8,      bColOff = ((lane >> 3) & 1) * 8;

    float c[2][8][4];
#pragma unroll
    for (int i = 0; i < 2; i++)
#pragma unroll
        for (int j = 0; j < 8; j++)
#pragma unroll
            for (int e = 0; e < 4; e++) c[i][j][e] = 0.0f;

    int nch = K >> 6;
    auto load = [&](int ch, int s) {
        int k0 = ch * 64;
#pragma unroll
        for (int i = 0; i < 4; i++) {
            int qd = tid + i * 256;
            int row = qd >> 3, c8 = qd & 7;
            int mg = (m0 + row < M) ? m0 + row : M - 1;
            cp16(sbase + (uint32_t)(s * 9216 + row * 72 + c8 * 8) * 2,
                 A + (size_t)mg * K + k0 + c8 * 8, (m0 + row < M) ? 16 : 0);
        }
#pragma unroll
        for (int i = 0; i < 4; i++) {
            int qd = tid + i * 256;
            int row = qd >> 3, c8 = qd & 7;
            cp16(sbase + (uint32_t)(27648 + s * 9216 + row * 72 + c8 * 8) * 2,
                 Bw + (size_t)(n0 + row) * K + k0 + c8 * 8, 16);
        }
        CP_COMMIT;
    };

    load(0, 0);
    if (nch > 1) load(1, 1);
    for (int ch = 0; ch < nch; ch++) {
        int s = ch % 3;
        if (ch + 1 < nch) { CP_WAIT1; } else { CP_WAIT0; }
        __syncthreads();
        if (ch + 2 < nch) load(ch + 2, (ch + 2) % 3);
        uint32_t aBase = sbase + (uint32_t)(s * 9216) * 2;
        uint32_t bBase = sbase + (uint32_t)(27648 + s * 9216) * 2;
#pragma unroll
        for (int ks = 0; ks < 4; ks++) {
            uint32_t a[2][4], b[8][2];
#pragma unroll
            for (int mt = 0; mt < 2; mt++)
                ldmx4(a[mt][0], a[mt][1], a[mt][2], a[mt][3],
                      aBase + (uint32_t)((wm0 + mt * 16 + aRowOff) * 72
                                         + ks * 16 + aColOff) * 2);
#pragma unroll
            for (int np = 0; np < 4; np++)
                ldmx4(b[2*np][0], b[2*np][1], b[2*np+1][0], b[2*np+1][1],
                      bBase + (uint32_t)((wn0 + np * 16 + bRowOff) * 72
                                         + ks * 16 + bColOff) * 2);
#pragma unroll
            for (int mt = 0; mt < 2; mt++)
#pragma unroll
                for (int nt = 0; nt < 8; nt++)
                    mma16(c[mt][nt], a[mt], b[nt][0], b[nt][1]);
        }
    }

#pragma unroll
    for (int mt = 0; mt < 2; mt++) {
#pragma unroll
        for (int nt = 0; nt < 8; nt++) {
            int col = n0 + wn0 + nt * 8 + tig * 2;
            float b0 = bias[col], b1 = bias[col + 1];
#pragma unroll
            for (int h2 = 0; h2 < 2; h2++) {
                int row = m0 + wm0 + mt * 16 + gid + h2 * 8;
                if (row >= M) continue;
                float v0 = c[mt][nt][h2 * 2] + b0;
                float v1 = c[mt][nt][h2 * 2 + 1] + b1;
                __half* cp_ = C + (size_t)row * N + col;
                if (EPI == 1) {
                    __half2 old = *(__half2*)cp_;
                    float2 of = __half22float2(old);
                    v0 += of.x; v1 += of.y;
                }
                if (EPI == 2) { v0 = gelu_f(v0); v1 = gelu_f(v1); }
                *(__half2*)cp_ = __floats2half2_rn(v0, v1);
            }
        }
    }
}

// ------------------------- patch embed GEMM (fp16 mma) -----------------------
#define DG_SMEM_P ((3*9216 + 3*128*72)*2)

__global__ void __launch_bounds__(256)
patch_mma(const __half* __restrict__ xh, const __half* __restrict__ cwh,
          const float* __restrict__ cb, const float* __restrict__ pos,
          __half* __restrict__ h)
{
    extern __shared__ __align__(16) __half smh[];
    uint32_t sbase = smem_u32(smh);
    int tid = threadIdx.x, lane = tid & 31, w = tid >> 5;
    int gid = lane >> 2, tig = lane & 3;
    int wm0 = (w & 3) * 32, wn0 = (w >> 2) * 64;
    int m0 = blockIdx.y * 128, n0 = blockIdx.x * 128;
    int l8 = lane & 7;
    int aRowOff = ((lane >> 3) & 1) * 8 + l8, aColOff = (lane >> 4) * 8;
    int bRowOff = (lane >> 4) * 8 + l8,      bColOff = ((lane >> 3) & 1) * 8;

    float c[2][8][4];
#pragma unroll
    for (int i = 0; i < 2; i++)
#pragma unroll
        for (int j = 0; j < 8; j++)
#pragma unroll
            for (int e = 0; e < 4; e++) c[i][j][e] = 0.0f;

    const __half* abase[4];
#pragma unroll
    for (int i = 0; i < 4; i++) {
        int qd = tid + i * 256;
        int row = qd >> 3;
        int mg = m0 + row;
        int b = mg >> 10, pi = mg & 1023;
        int ii = pi >> 5, jj = pi & 31;
        abase[i] = xh + ((size_t)(b * 3) * 512 + ii * 16) * 512 + jj * 16;
    }

    auto load = [&](int ch, int s) {
        int k0 = ch * 64;
#pragma unroll
        for (int i = 0; i < 4; i++) {
            int qd = tid + i * 256;
            int row = qd >> 3, c8 = qd & 7;
            int k = k0 + c8 * 8;
            int cc = k >> 8, rr = (k >> 4) & 15, qq = k & 15;
            cp16(sbase + (uint32_t)(s * 9216 + row * 72 + c8 * 8) * 2,
                 abase[i] + (size_t)cc * 262144 + rr * 512 + qq, 16);
        }
#pragma unroll
        for (int i = 0; i < 4; i++) {
            int qd = tid + i * 256;
            int row = qd >> 3, c8 = qd & 7;
            cp16(sbase + (uint32_t)(27648 + s * 9216 + row * 72 + c8 * 8) * 2,
                 cwh + (size_t)(n0 + row) * PK + k0 + c8 * 8, 16);
        }
        CP_COMMIT;
    };

    load(0, 0);
    load(1, 1);
    for (int ch = 0; ch < 12; ch++) {
        int s = ch % 3;
        if (ch + 1 < 12) { CP_WAIT1; } else { CP_WAIT0; }
        __syncthreads();
        if (ch + 2 < 12) load(ch + 2, (ch + 2) % 3);
        uint32_t aBase = sbase + (uint32_t)(s * 9216) * 2;
        uint32_t bBase = sbase + (uint32_t)(27648 + s * 9216) * 2;
#pragma unroll
        for (int ks = 0; ks < 4; ks++) {
            uint32_t a[2][4], b[8][2];
#pragma unroll
            for (int mt = 0; mt < 2; mt++)
                ldmx4(a[mt][0], a[mt][1], a[mt][2], a[mt][3],
                      aBase + (uint32_t)((wm0 + mt * 16 + aRowOff) * 72
                                         + ks * 16 + aColOff) * 2);
#pragma unroll
            for (int np = 0; np < 4; np++)
                ldmx4(b[2*np][0], b[2*np][1], b[2*np+1][0], b[2*np+1][1],
                      bBase + (uint32_t)((wn0 + np * 16 + bRowOff) * 72
                                         + ks * 16 + bColOff) * 2);
#pragma unroll
            for (int mt = 0; mt < 2; mt++)
#pragma unroll
                for (int nt = 0; nt < 8; nt++)
                    mma16(c[mt][nt], a[mt], b[nt][0], b[nt][1]);
        }
    }

#pragma unroll
    for (int mt = 0; mt < 2; mt++) {
#pragma unroll
        for (int h2 = 0; h2 < 2; h2++) {
            int mg = m0 + wm0 + mt * 16 + gid + h2 * 8;
            int b = mg >> 10, pi = mg & 1023;
            __half* hp = h + (size_t)(b * SS + 1 + pi) * HH;
            const float* pp = pos + (size_t)(1 + pi) * HH;
#pragma unroll
            for (int nt = 0; nt < 8; nt++) {
                int col = n0 + wn0 + nt * 8 + tig * 2;
                float v0 = c[mt][nt][h2 * 2]     + cb[col]     + pp[col];
                float v1 = c[mt][nt][h2 * 2 + 1] + cb[col + 1] + pp[col + 1];
                *(__half2*)(hp + col) = __floats2half2_rn(v0, v1);
            }
        }
    }
}

// ------------------------- flash attention (fp16, 3-stage) -------------------
// Scores in log2 domain; P = ex2.f16x2; row sums via ones-column mma.
// Chunks 0..7 are full (all keys valid, no masking). Chunk 8 has exactly one
// valid key (1024) and runs a specialized cheap tail (bit-identical results:
// skipped terms were exact +0.0 contributions).
#define FA_SMEM (6*9216*2)
#define FA_VOFF 27648
#define NCHK 9

__global__ void __launch_bounds__(256)
flash_attn(const __half* __restrict__ qkv, __half* __restrict__ out)
{
    extern __shared__ __align__(16) __half smh[];
    uint32_t sbase = smem_u32(smh);
    int tid = threadIdx.x, lane = tid & 31, w = tid >> 5;
    int gid = lane >> 2, tig = lane & 3;
    int bh = blockIdx.y, bi = bh / NHH, hd = bh % NHH;
    int m0 = blockIdx.x * 128;
    int wm0 = w * 16;
    int l8 = lane & 7;
    int kRowOff = (lane >> 4) * 8 + l8, kColOff = ((lane >> 3) & 1) * 8;
    int lrow2 = lane & 15;
    int lrow = ((lane >> 3) & 1) * 8 + l8;
    int lcol = (lane >> 4) * 8;

    // ---- ones column in V padding (col 64 = 1, cols 65-71 = 0), all 3 stages
    for (int r = tid; r < 384; r += 256) {
        int s = r >> 7, row = r & 127;
        uint32_t* vp = (uint32_t*)(smh + FA_VOFF + s * 9216 + row * 72 + 64);
        vp[0] = 0x00003C00u; vp[1] = 0u; vp[2] = 0u; vp[3] = 0u;
    }

    // ---- Q fragments, pre-scaled by log2(e)/8 (fp32 math, fp16 pack) ----
    const float QS = 0.18033688011112042f;
    uint32_t qa[4][4];
    {
        int r0 = m0 + wm0 + gid, r1 = r0 + 8;
        const __half* q0 = qkv + (size_t)(bi * SS + (r0 < SS ? r0 : 0)) * QKVN + hd * 64;
        const __half* q1 = qkv + (size_t)(bi * SS + (r1 < SS ? r1 : 0)) * QKVN + hd * 64;
        float z0 = (r0 < SS) ? QS : 0.0f;
        float z1 = (r1 < SS) ? QS : 0.0f;
#pragma unroll
        for (int ks = 0; ks < 4; ks++) {
            __half2 t;
            t = __floats2half2_rn(__half2float(q0[ks*16 + tig*2]) * z0,
                                  __half2float(q0[ks*16 + tig*2 + 1]) * z0);
            qa[ks][0] = *(uint32_t*)&t;
            t = __floats2half2_rn(__half2float(q1[ks*16 + tig*2]) * z1,
                                  __half2float(q1[ks*16 + tig*2 + 1]) * z1);
            qa[ks][1] = *(uint32_t*)&t;
            t = __floats2half2_rn(__half2float(q0[ks*16 + 8 + tig*2]) * z0,
                                  __half2float(q0[ks*16 + 8 + tig*2 + 1]) * z0);
            qa[ks][2] = *(uint32_t*)&t;
            t = __floats2half2_rn(__half2float(q1[ks*16 + 8 + tig*2]) * z1,
                                  __half2float(q1[ks*16 + 8 + tig*2 + 1]) * z1);
            qa[ks][3] = *(uint32_t*)&t;
        }
    }

    float o[8][4];
#pragma unroll
    for (int i = 0; i < 8; i++)
#pragma unroll
        for (int e = 0; e < 4; e++) o[i][e] = 0.0f;
    float ol[4] = {0.0f, 0.0f, 0.0f, 0.0f};
    float m_run[2] = {-1e30f, -1e30f};

    auto loadKV = [&](int c, int s) {
        int jb = c * 128;
#pragma unroll
        for (int i = 0; i < 4; i++) {
            int qd = tid + i * 256;
            int row = qd >> 3, c8 = qd & 7;
            int j = jb + row;
            const __half* src = qkv + (size_t)(bi * SS + (j < SS ? j : 0)) * QKVN
                              + 384 + hd * 64 + c8 * 8;
            cp16(sbase + (uint32_t)(s * 9216 + row * 72 + c8 * 8) * 2, src,
                 (j < SS) ? 16 : 0);
        }
#pragma unroll
        for (int i = 0; i < 4; i++) {
            int qd = tid + i * 256;
            int row = qd >> 3, c8 = qd & 7;
            int j = jb + row;
            const __half* src = qkv + (size_t)(bi * SS + (j < SS ? j : 0)) * QKVN
                              + 768 + hd * 64 + c8 * 8;
            cp16(sbase + (uint32_t)(FA_VOFF + s * 9216 + row * 72 + c8 * 8) * 2, src,
                 (j < SS) ? 16 : 0);
        }
        CP_COMMIT;
    };

    loadKV(0, 0);
    loadKV(1, 1);

    // ---- main loop: full chunks 0..7, no masking needed ----
    for (int c = 0; c < NCHK - 1; c++) {
        int s = c % 3;
        CP_WAIT1;
        __syncthreads();
        if (c + 2 < NCHK) loadKV(c + 2, (c + 2) % 3);
        uint32_t kBase = sbase + (uint32_t)(s * 9216) * 2;
        uint32_t vbase = sbase + (uint32_t)(FA_VOFF + s * 9216) * 2;

        float sc[16][4];
#pragma unroll
        for (int i = 0; i < 16; i++)
#pragma unroll
            for (int e = 0; e < 4; e++) sc[i][e] = 0.0f;
#pragma unroll
        for (int ks = 0; ks < 4; ks++) {
#pragma unroll
            for (int np = 0; np < 8; np++) {
                uint32_t r0, r1, r2, r3;
                ldmx4(r0, r1, r2, r3,
                      kBase + (uint32_t)((np * 16 + kRowOff) * 72
                                         + ks * 16 + kColOff) * 2);
                mma16(sc[2*np],     qa[ks], r0, r1);
                mma16(sc[2*np + 1], qa[ks], r2, r3);
            }
        }

#pragma unroll
        for (int h2 = 0; h2 < 2; h2++) {
            float mx = -1e30f;
#pragma unroll
            for (int nt = 0; nt < 16; nt++)
                mx = fmaxf(mx, fmaxf(sc[nt][h2 * 2], sc[nt][h2 * 2 + 1]));
            mx = fmaxf(mx, __shfl_xor_sync(0xffffffffu, mx, 1));
            mx = fmaxf(mx, __shfl_xor_sync(0xffffffffu, mx, 2));
            float mnew = fmaxf(m_run[h2], mx);
            float corr = exp2f(m_run[h2] - mnew);
            m_run[h2] = mnew;
#pragma unroll
            for (int ng = 0; ng < 8; ng++) {
                o[ng][h2 * 2] *= corr;
                o[ng][h2 * 2 + 1] *= corr;
            }
            ol[h2 * 2] *= corr;
            ol[h2 * 2 + 1] *= corr;
        }

        float m0f = m_run[0], m1f = m_run[1];
#pragma unroll
        for (int ks = 0; ks < 8; ks++) {
            uint32_t pa[4];
            __half2 t;
            t = __floats2half2_rn(sc[2*ks][0] - m0f, sc[2*ks][1] - m0f);
            pa[0] = h2ex2(*(uint32_t*)&t);
            t = __floats2half2_rn(sc[2*ks][2] - m1f, sc[2*ks][3] - m1f);
            pa[1] = h2ex2(*(uint32_t*)&t);
            t = __floats2half2_rn(sc[2*ks+1][0] - m0f, sc[2*ks+1][1] - m0f);
            pa[2] = h2ex2(*(uint32_t*)&t);
            t = __floats2half2_rn(sc[2*ks+1][2] - m1f, sc[2*ks+1][3] - m1f);
            pa[3] = h2ex2(*(uint32_t*)&t);
#pragma unroll
            for (int np = 0; np < 4; np++) {
                uint32_t r0, r1, r2, r3;
                uint32_t addr = vbase
                    + (uint32_t)((ks * 16 + lrow) * 72 + np * 16 + lcol) * 2;
                ldmx4t(r0, r1, r2, r3, addr);
                mma16(o[np * 2],     pa, r0, r1);
                mma16(o[np * 2 + 1], pa, r2, r3);
            }
            uint32_t v0, v1;
            ldmx2t(v0, v1, vbase + (uint32_t)((ks * 16 + lrow2) * 72 + 64) * 2);
            mma16(ol, pa, v0, v1);
        }
    }

    // ---- tail chunk (c = 8): only key 1024 (col 0) valid ----
    {
        CP_WAIT0;
        __syncthreads();
        const int s = (NCHK - 1) % 3;   // 2
        uint32_t kBase = sbase + (uint32_t)(s * 9216) * 2;
        uint32_t vbase = sbase + (uint32_t)(FA_VOFF + s * 9216) * 2;

        float tsc[2][4];
#pragma unroll
        for (int i = 0; i < 2; i++)
#pragma unroll
            for (int e = 0; e < 4; e++) tsc[i][e] = 0.0f;
#pragma unroll
        for (int ks = 0; ks < 4; ks++) {
            uint32_t r0, r1, r2, r3;
            ldmx4(r0, r1, r2, r3,
                  kBase + (uint32_t)(kRowOff * 72 + ks * 16 + kColOff) * 2);
            mma16(tsc[0], qa[ks], r0, r1);
            mma16(tsc[1], qa[ks], r2, r3);
        }
        // mask: tsc[nt][e] holds col nt*8 + tig*2 + (e&1); only col 0 valid
#pragma unroll
        for (int nt = 0; nt < 2; nt++)
#pragma unroll
            for (int e = 0; e < 4; e++) {
                int col = nt * 8 + tig * 2 + (e & 1);
                if (col != 0) tsc[nt][e] = -1e30f;
            }
#pragma unroll
        for (int h2 = 0; h2 < 2; h2++) {
            float mx = fmaxf(fmaxf(tsc[0][h2 * 2], tsc[0][h2 * 2 + 1]),
                             fmaxf(tsc[1][h2 * 2], tsc[1][h2 * 2 + 1]));
            mx = fmaxf(mx, __shfl_xor_sync(0xffffffffu, mx, 1));
            mx = fmaxf(mx, __shfl_xor_sync(0xffffffffu, mx, 2));
            float mnew = fmaxf(m_run[h2], mx);
            float corr = exp2f(m_run[h2] - mnew);
            m_run[h2] = mnew;
#pragma unroll
            for (int ng = 0; ng < 8; ng++) {
                o[ng][h2 * 2] *= corr;
                o[ng][h2 * 2 + 1] *= corr;
            }
            ol[h2 * 2] *= corr;
            ol[h2 * 2 + 1] *= corr;
        }
        float m0f = m_run[0], m1f = m_run[1];
        uint32_t pa[4];
        __half2 t;
        t = __floats2half2_rn(tsc[0][0] - m0f, tsc[0][1] - m0f);
        pa[0] = h2ex2(*(uint32_t*)&t);
        t = __floats2half2_rn(tsc[0][2] - m1f, tsc[0][3] - m1f);
        pa[1] = h2ex2(*(uint32_t*)&t);
        t = __floats2half2_rn(tsc[1][0] - m0f, tsc[1][1] - m0f);
        pa[2] = h2ex2(*(uint32_t*)&t);
        t = __floats2half2_rn(tsc[1][2] - m1f, tsc[1][3] - m1f);
        pa[3] = h2ex2(*(uint32_t*)&t);
#pragma unroll
        for (int np = 0; np < 4; np++) {
            uint32_t r0, r1, r2, r3;
            ldmx4t(r0, r1, r2, r3,
                   vbase + (uint32_t)(lrow * 72 + np * 16 + lcol) * 2);
            mma16(o[np * 2],     pa, r0, r1);
            mma16(o[np * 2 + 1], pa, r2, r3);
        }
        uint32_t v0, v1;
        ldmx2t(v0, v1, vbase + (uint32_t)(lrow2 * 72 + 64) * 2);
        mma16(ol, pa, v0, v1);
    }

    // ---- epilogue: l lives in ol col 64 (tig==0 lanes) ----
#pragma unroll
    for (int h2 = 0; h2 < 2; h2++) {
        int i = m0 + wm0 + gid + h2 * 8;
        float lv = __shfl_sync(0xffffffffu, ol[h2 * 2], lane & ~3);
        if (i >= SS) continue;
        float invl = 1.0f / lv;
        __half* op = out + (size_t)(bi * SS + i) * HH + hd * 64;
#pragma unroll
        for (int ng = 0; ng < 8; ng++) {
            int d = ng * 8 + tig * 2;
            *(__half2*)(op + d) = __floats2half2_rn(o[ng][h2 * 2] * invl,
                                                    o[ng][h2 * 2 + 1] * invl);
        }
    }
}

// -------------------------- weight prep -------------------------------------
__global__ void transcvt(const float* __restrict__ in, __half* __restrict__ out,
                         int K, int N, size_t outLayerStride, int rowOff)
{
    __shared__ float tile[32][33];
    int l = blockIdx.z;
    int k0 = blockIdx.y * 32, n0 = blockIdx.x * 32;
    const float* ip = in + (size_t)l * K * N;
    __half* op = out + (size_t)l * outLayerStride + (size_t)rowOff * K;
    int tx = threadIdx.x, ty = threadIdx.y;
#pragma unroll
    for (int i = 0; i < 32; i += 8)
        tile[ty + i][tx] = ip[(size_t)(k0 + ty + i) * N + n0 + tx];
    __syncthreads();
#pragma unroll
    for (int i = 0; i < 32; i += 8)
        op[(size_t)(n0 + ty + i) * K + k0 + tx] = __float2half(tile[tx][ty + i]);
}

__global__ void cvt_half4(const float* __restrict__ in, __half* __restrict__ out,
                          int n4)
{
    int i = blockIdx.x * 256 + threadIdx.x;
    if (i >= n4) return;
    float4 v = ((const float4*)in)[i];
    __half2 lo = __floats2half2_rn(v.x, v.y);
    __half2 hi = __floats2half2_rn(v.z, v.w);
    ((__half2*)out)[i * 2]     = lo;
    ((__half2*)out)[i * 2 + 1] = hi;
}

__global__ void pack_qkv_b(const float* __restrict__ bq,
                           const float* __restrict__ bk,
                           const float* __restrict__ bv,
                           float* __restrict__ out)
{
    int idx = blockIdx.x * 256 + threadIdx.x;
    if (idx >= LL * QKVN) return;
    int n = idx % QKVN;
    int l = idx / QKVN;
    const float* src = (n < HH) ? bq : (n < 2 * HH) ? bk : bv;
    out[idx] = src[l * HH + n % HH];
}

__global__ void cls_pos_kernel(const float* __restrict__ cls,
                               const float* __restrict__ pos,
                               __half* __restrict__ h)
{
    int t = blockIdx.x * 256 + threadIdx.x;
    if (t < BB * HH) {
        int b = t / HH, o = t % HH;
        h[(size_t)(b * SS) * HH + o] = __float2half(cls[o] + pos[o]);
    }
}

// --------------------------- LayerNorm (vectorized, fp32 math) ---------------
// 192 threads per row; each thread handles one __half2 (2 elements).
__global__ void ln_kernel(const __half* __restrict__ in,
                          const float* __restrict__ w,
                          const float* __restrict__ b,
                          __half* __restrict__ out)
{
    int row = blockIdx.x;
    const __half2* p = (const __half2*)(in + (size_t)row * HH);
    int t = threadIdx.x;            // 192 threads = 6 warps
    float2 v = __half22float2(p[t]);

    __shared__ float sh[6];
    float s = v.x + v.y;
#pragma unroll
    for (int o = 16; o; o >>= 1) s += __shfl_xor_sync(0xffffffffu, s, o);
    if ((t & 31) == 0) sh[t >> 5] = s;
    __syncthreads();
    float mu = (sh[0] + sh[1] + sh[2] + sh[3] + sh[4] + sh[5]) * (1.0f / 384.0f);
    __syncthreads();

    float d0 = v.x - mu, d1 = v.y - mu;
    float sq = d0 * d0 + d1 * d1;
#pragma unroll
    for (int o = 16; o; o >>= 1) sq += __shfl_xor_sync(0xffffffffu, sq, o);
    if ((t & 31) == 0) sh[t >> 5] = sq;
    __syncthreads();
    float var = (sh[0] + sh[1] + sh[2] + sh[3] + sh[4] + sh[5]) * (1.0f / 384.0f);
    float inv = rsqrtf(var + 1e-5f);

    float2 wv = ((const float2*)w)[t];
    float2 bv = ((const float2*)b)[t];
    __half2* q = (__half2*)(out + (size_t)row * HH);
    q[t] = __floats2half2_rn(d0 * inv * wv.x + bv.x, d1 * inv * wv.y + bv.y);
}

// ------------------------------- classifier ---------------------------------
__global__ void classifier_kernel(const __half* __restrict__ h,
                                  const float* __restrict__ wc,
                                  const float* __restrict__ bc,
                                  float* __restrict__ out)
{
    int t = blockIdx.x * 256 + threadIdx.x;
    if (t >= BB * NCC) return;
    int b = t / NCC, n = t % NCC;
    const __half* hp = h + (size_t)(b * SS) * HH;
    float acc = 0.0f;
    for (int k = 0; k < HH; k++) acc += __half2float(hp[k]) * wc[(size_t)k * NCC + n];
    out[t] = acc + bc[n];
}

// ------------------------------- host side ----------------------------------
extern "C" void kernel_launch(void* const* d_in, const int* in_sizes, int n_in,
                              void* d_out, int out_size)
{
    const float* x    = (const float*)d_in[0];
    const float* cw   = (const float*)d_in[1];
    const float* cb   = (const float*)d_in[2];
    const float* cls  = (const float*)d_in[3];
    const float* pos  = (const float*)d_in[4];
    const float* ln1w = (const float*)d_in[5];
    const float* ln1b = (const float*)d_in[6];
    const float* wq   = (const float*)d_in[7];
    const float* bq   = (const float*)d_in[8];
    const float* wk   = (const float*)d_in[9];
    const float* bk   = (const float*)d_in[10];
    const float* wv   = (const float*)d_in[11];
    const float* bv   = (const float*)d_in[12];
    const float* wo   = (const float*)d_in[13];
    const float* bo   = (const float*)d_in[14];
    const float* ln2w = (const float*)d_in[15];
    const float* ln2b = (const float*)d_in[16];
    const float* w1   = (const float*)d_in[17];
    const float* b1   = (const float*)d_in[18];
    const float* w2   = (const float*)d_in[19];
    const float* b2   = (const float*)d_in[20];
    const float* wc   = (const float*)d_in[21];
    const float* bc   = (const float*)d_in[22];

    __half *h, *hn, *qkv, *attn, *mlp, *xh, *cwh;
    __half *wqkv, *wot, *w1t, *w2t; float *bqkv;
    cudaGetSymbolAddress((void**)&h,    g_h);
    cudaGetSymbolAddress((void**)&hn,   g_hn);
    cudaGetSymbolAddress((void**)&qkv,  g_qkv);
    cudaGetSymbolAddress((void**)&attn, g_attn);
    cudaGetSymbolAddress((void**)&mlp,  g_mlp);
    cudaGetSymbolAddress((void**)&xh,   g_xh);
    cudaGetSymbolAddress((void**)&cwh,  g_cwh);
    cudaGetSymbolAddress((void**)&wqkv, g_wqkv);
    cudaGetSymbolAddress((void**)&bqkv, g_bqkv);
    cudaGetSymbolAddress((void**)&wot,  g_wot);
    cudaGetSymbolAddress((void**)&w1t,  g_w1t);
    cudaGetSymbolAddress((void**)&w2t,  g_w2t);

    // weight/input prep
    {
        dim3 tb(32, 8);
        transcvt<<<dim3(HH/32, HH/32, LL), tb>>>(wq, wqkv, HH, HH, (size_t)QKVN*HH, 0);
        transcvt<<<dim3(HH/32, HH/32, LL), tb>>>(wk, wqkv, HH, HH, (size_t)QKVN*HH, HH);
        transcvt<<<dim3(HH/32, HH/32, LL), tb>>>(wv, wqkv, HH, HH, (size_t)QKVN*HH, 2*HH);
        transcvt<<<dim3(HH/32, HH/32, LL), tb>>>(wo, wot, HH, HH, (size_t)HH*HH, 0);
        transcvt<<<dim3(II/32, HH/32, LL), tb>>>(w1, w1t, HH, II, (size_t)II*HH, 0);
        transcvt<<<dim3(HH/32, II/32, LL), tb>>>(w2, w2t, II, HH, (size_t)HH*II, 0);
        pack_qkv_b<<<(LL*QKVN + 255)/256, 256>>>(bq, bk, bv, bqkv);
        int nx4 = (BB*3*512*512)/4;
        cvt_half4<<<(nx4 + 255)/256, 256>>>(x, xh, nx4);
        int nw4 = (HH*PK)/4;
        cvt_half4<<<(nw4 + 255)/256, 256>>>(cw, cwh, nw4);
    }

    cudaFuncSetAttribute((const void*)mma_gemm<0>, cudaFuncAttributeMaxDynamicSharedMemorySize, DG_SMEM);
    cudaFuncSetAttribute((const void*)mma_gemm<1>, cudaFuncAttributeMaxDynamicSharedMemorySize, DG_SMEM);
    cudaFuncSetAttribute((const void*)mma_gemm<2>, cudaFuncAttributeMaxDynamicSharedMemorySize, DG_SMEM);
    cudaFuncSetAttribute((const void*)patch_mma, cudaFuncAttributeMaxDynamicSharedMemorySize, DG_SMEM_P);
    cudaFuncSetAttribute((const void*)flash_attn, cudaFuncAttributeMaxDynamicSharedMemorySize, FA_SMEM);

    patch_mma<<<dim3(HH/128, MPATCH/128), 256, DG_SMEM_P>>>(xh, cwh, cb, pos, h);
    cls_pos_kernel<<<(BB * HH + 255) / 256, 256>>>(cls, pos, h);

    int mt = (MTOK + 127) / 128;                 // 129
    dim3 gQKV(QKVN / 128, mt);                   // (9, 129)
    dim3 g384(HH / 128, mt);                     // (3, 129)
    dim3 g1536(II / 128, mt);                    // (12, 129)
    dim3 gFA((SS + 127) / 128, BB * NHH);        // (9, 96)

    for (int l = 0; l < LL; l++) {
        ln_kernel<<<MTOK, 192>>>(h, ln1w + l * HH, ln1b + l * HH, hn);
        mma_gemm<0><<<gQKV, 256, DG_SMEM>>>(hn, wqkv + (size_t)l * QKVN * HH,
                                            bqkv + l * QKVN, qkv, MTOK, QKVN, HH);
        flash_attn<<<gFA, 256, FA_SMEM>>>(qkv, attn);
        mma_gemm<1><<<g384, 256, DG_SMEM>>>(attn, wot + (size_t)l * HH * HH,
                                            bo + l * HH, h, MTOK, HH, HH);
        ln_kernel<<<MTOK, 192>>>(h, ln2w + l * HH, ln2b + l * HH, hn);
        mma_gemm<2><<<g1536, 256, DG_SMEM>>>(hn, w1t + (size_t)l * II * HH,
                                             b1 + l * II, mlp, MTOK, II, HH);
        mma_gemm<1><<<g384, 256, DG_SMEM>>>(mlp, w2t + (size_t)l * HH * II,
                                            b2 + l * HH, h, MTOK, HH, II);
    }

    classifier_kernel<<<(BB * NCC + 255) / 256, 256>>>(h, wc, bc, (float*)d_out);
}

// round 15
// speedup vs baseline: 1.0322x; 1.0322x over previous
#include <cuda_runtime.h>
#include <cuda_fp16.h>
#include <math.h>
#include <stdint.h>

#define BB 16
#define SS 1025
#define HH 384
#define NHH 6
#define LL 12
#define II 1536
#define NCC 1000
#define MTOK (BB*SS)       // 16400
#define NPATCH 1024
#define MPATCH (BB*NPATCH) // 16384
#define QKVN 1152          // 3*HH
#define PK 768             // patch K = 3*16*16

// ---------------- scratch (__device__ globals; allocation-free rule) -------
__device__ __align__(256) __half g_h[MTOK*HH];          // fp16 residual stream
__device__ __align__(256) __half g_hn[MTOK*HH];
__device__ __align__(256) __half g_qkv[(size_t)MTOK*QKVN];
__device__ __align__(256) __half g_attn[MTOK*HH];
__device__ __align__(256) __half g_mlp[MTOK*II];
__device__ __align__(256) __half g_xh[(size_t)BB*3*512*512];
__device__ __align__(256) __half g_cwh[HH*PK];
// fp16 weights, pre-transposed to [L][N][K]
__device__ __align__(256) __half g_wqkv[(size_t)LL*QKVN*HH];
__device__ __align__(256) float  g_bqkv[LL*QKVN];
__device__ __align__(256) __half g_wot[LL*HH*HH];
__device__ __align__(256) __half g_w1t[(size_t)LL*II*HH];
__device__ __align__(256) __half g_w2t[(size_t)LL*HH*II];

// ---------------------------- helpers ---------------------------------------
__device__ __forceinline__ uint32_t smem_u32(const void* p) {
    uint32_t a;
    asm("{ .reg .u64 t; cvta.to.shared.u64 t, %1; cvt.u32.u64 %0, t; }"
        : "=r"(a) : "l"(p));
    return a;
}

__device__ __forceinline__ void cp16(uint32_t dst, const void* src, int nbytes) {
    asm volatile("cp.async.cg.shared.global [%0], [%1], 16, %2;"
                 :: "r"(dst), "l"(src), "r"(nbytes) : "memory");
}
#define CP_COMMIT asm volatile("cp.async.commit_group;" ::: "memory")
#define CP_WAIT0  asm volatile("cp.async.wait_group 0;" ::: "memory")
#define CP_WAIT1  asm volatile("cp.async.wait_group 1;" ::: "memory")

__device__ __forceinline__ void mma16(float* c, const uint32_t* a,
                                      uint32_t b0, uint32_t b1) {
    asm volatile("mma.sync.aligned.m16n8k16.row.col.f32.f16.f16.f32 "
        "{%0,%1,%2,%3}, {%4,%5,%6,%7}, {%8,%9}, {%0,%1,%2,%3};"
        : "+f"(c[0]), "+f"(c[1]), "+f"(c[2]), "+f"(c[3])
        : "r"(a[0]), "r"(a[1]), "r"(a[2]), "r"(a[3]), "r"(b0), "r"(b1));
}

__device__ __forceinline__ void ldmx4(uint32_t& r0, uint32_t& r1,
                                      uint32_t& r2, uint32_t& r3, uint32_t addr) {
    asm volatile("ldmatrix.sync.aligned.m8n8.x4.shared.b16 {%0,%1,%2,%3}, [%4];"
        : "=r"(r0), "=r"(r1), "=r"(r2), "=r"(r3) : "r"(addr));
}

__device__ __forceinline__ void ldmx4t(uint32_t& r0, uint32_t& r1,
                                       uint32_t& r2, uint32_t& r3, uint32_t addr) {
    asm volatile("ldmatrix.sync.aligned.m8n8.x4.trans.shared.b16 {%0,%1,%2,%3}, [%4];"
        : "=r"(r0), "=r"(r1), "=r"(r2), "=r"(r3) : "r"(addr));
}

__device__ __forceinline__ void ldmx2t(uint32_t& r0, uint32_t& r1, uint32_t addr) {
    asm volatile("ldmatrix.sync.aligned.m8n8.x2.trans.shared.b16 {%0,%1}, [%2];"
        : "=r"(r0), "=r"(r1) : "r"(addr));
}

__device__ __forceinline__ uint32_t h2ex2(uint32_t x) {
    uint32_t r;
    asm("ex2.approx.f16x2 %0, %1;" : "=r"(r) : "r"(x));
    return r;
}

__device__ __forceinline__ float gelu_f(float u) {
    float a = -1.5957691216057308f * (u + 0.044715f * u * u * u);
    float e = __expf(fminf(a, 80.0f));
    float th = (1.0f - e) / (1.0f + e);
    return 0.5f * u * (1.0f + th);
}

// ------------------------- dense mma GEMM (fp16) -----------------------------
// C[M,N] = A[M,K] @ W^T (W stored [N][K]) + bias. All outputs fp16.
// EPI 0: bias; 1: bias + residual (C += old, fp32 math); 2: bias + gelu
// Block 128x128, 256 thr (8 warps: 4m x 2n), warp 32x64, K-chunk 64, 3 stages.
// EPI 0/2: epilogue staged through smem for coalesced 16B stores (bit-exact).
#define DG_SMEM (6*9216*2)

template <int EPI>
__global__ void __launch_bounds__(256)
mma_gemm(const __half* __restrict__ A, const __half* __restrict__ Bw,
         const float* __restrict__ bias, __half* __restrict__ C,
         int M, int N, int K)
{
    extern __shared__ __align__(16) __half smh[];
    uint32_t sbase = smem_u32(smh);
    int tid = threadIdx.x, lane = tid & 31, w = tid >> 5;
    int gid = lane >> 2, tig = lane & 3;
    int wm0 = (w & 3) * 32, wn0 = (w >> 2) * 64;
    int m0 = blockIdx.y * 128, n0 = blockIdx.x * 128;
    int l8 = lane & 7;
    int aRowOff = ((lane >> 3) & 1) * 8 + l8, aColOff = (lane >> 4) * 8;
    int bRowOff = (lane >> 4) * 8 + l8,      bColOff = ((lane >> 3) & 1) * 8;

    float c[2][8][4];
#pragma unroll
    for (int i = 0; i < 2; i++)
#pragma unroll
        for (int j = 0; j < 8; j++)
#pragma unroll
            for (int e = 0; e < 4; e++) c[i][j][e] = 0.0f;

    int nch = K >> 6;
    auto load = [&](int ch, int s) {
        int k0 = ch * 64;
#pragma unroll
        for (int i = 0; i < 4; i++) {
            int qd = tid + i * 256;
            int row = qd >> 3, c8 = qd & 7;
            int mg = (m0 + row < M) ? m0 + row : M - 1;
            cp16(sbase + (uint32_t)(s * 9216 + row * 72 + c8 * 8) * 2,
                 A + (size_t)mg * K + k0 + c8 * 8, (m0 + row < M) ? 16 : 0);
        }
#pragma unroll
        for (int i = 0; i < 4; i++) {
            int qd = tid + i * 256;
            int row = qd >> 3, c8 = qd & 7;
            cp16(sbase + (uint32_t)(27648 + s * 9216 + row * 72 + c8 * 8) * 2,
                 Bw + (size_t)(n0 + row) * K + k0 + c8 * 8, 16);
        }
        CP_COMMIT;
    };

    load(0, 0);
    if (nch > 1) load(1, 1);
    for (int ch = 0; ch < nch; ch++) {
        int s = ch % 3;
        if (ch + 1 < nch) { CP_WAIT1; } else { CP_WAIT0; }
        __syncthreads();
        if (ch + 2 < nch) load(ch + 2, (ch + 2) % 3);
        uint32_t aBase = sbase + (uint32_t)(s * 9216) * 2;
        uint32_t bBase = sbase + (uint32_t)(27648 + s * 9216) * 2;
#pragma unroll
        for (int ks = 0; ks < 4; ks++) {
            uint32_t a[2][4], b[8][2];
#pragma unroll
            for (int mt = 0; mt < 2; mt++)
                ldmx4(a[mt][0], a[mt][1], a[mt][2], a[mt][3],
                      aBase + (uint32_t)((wm0 + mt * 16 + aRowOff) * 72
                                         + ks * 16 + aColOff) * 2);
#pragma unroll
            for (int np = 0; np < 4; np++)
                ldmx4(b[2*np][0], b[2*np][1], b[2*np+1][0], b[2*np+1][1],
                      bBase + (uint32_t)((wn0 + np * 16 + bRowOff) * 72
                                         + ks * 16 + bColOff) * 2);
#pragma unroll
            for (int mt = 0; mt < 2; mt++)
#pragma unroll
                for (int nt = 0; nt < 8; nt++)
                    mma16(c[mt][nt], a[mt], b[nt][0], b[nt][1]);
        }
    }

    if (EPI == 1) {
        // residual path: scattered half2 stores (read dominates anyway)
#pragma unroll
        for (int mt = 0; mt < 2; mt++) {
#pragma unroll
            for (int nt = 0; nt < 8; nt++) {
                int col = n0 + wn0 + nt * 8 + tig * 2;
                float b0 = bias[col], b1 = bias[col + 1];
#pragma unroll
                for (int h2 = 0; h2 < 2; h2++) {
                    int row = m0 + wm0 + mt * 16 + gid + h2 * 8;
                    if (row >= M) continue;
                    float v0 = c[mt][nt][h2 * 2] + b0;
                    float v1 = c[mt][nt][h2 * 2 + 1] + b1;
                    __half* cp_ = C + (size_t)row * N + col;
                    __half2 old = *(__half2*)cp_;
                    float2 of = __half22float2(old);
                    *(__half2*)cp_ = __floats2half2_rn(v0 + of.x, v1 + of.y);
                }
            }
        }
    } else {
        // pure-store path: stage through smem, coalesced 16B global stores
        __syncthreads();   // all smem reads done; reuse A stages 0-1 (36.9KB)
#pragma unroll
        for (int mt = 0; mt < 2; mt++) {
#pragma unroll
            for (int nt = 0; nt < 8; nt++) {
                int colL = wn0 + nt * 8 + tig * 2;
                float b0 = bias[n0 + colL], b1 = bias[n0 + colL + 1];
#pragma unroll
                for (int h2 = 0; h2 < 2; h2++) {
                    int rl = wm0 + mt * 16 + gid + h2 * 8;
                    float v0 = c[mt][nt][h2 * 2] + b0;
                    float v1 = c[mt][nt][h2 * 2 + 1] + b1;
                    if (EPI == 2) { v0 = gelu_f(v0); v1 = gelu_f(v1); }
                    *(__half2*)(smh + rl * 136 + colL) = __floats2half2_rn(v0, v1);
                }
            }
        }
        __syncthreads();
#pragma unroll
        for (int i = 0; i < 8; i++) {
            int idx = tid + i * 256;
            int row = idx >> 4, chk = idx & 15;
            int mg = m0 + row;
            if (mg < M) {
                uint4 v = *(const uint4*)(smh + row * 136 + chk * 8);
                *(uint4*)(C + (size_t)mg * N + n0 + chk * 8) = v;
            }
        }
    }
}

// ------------------------- patch embed GEMM (fp16 mma) -----------------------
#define DG_SMEM_P ((3*9216 + 3*128*72)*2)

__global__ void __launch_bounds__(256)
patch_mma(const __half* __restrict__ xh, const __half* __restrict__ cwh,
          const float* __restrict__ cb, const float* __restrict__ pos,
          __half* __restrict__ h)
{
    extern __shared__ __align__(16) __half smh[];
    uint32_t sbase = smem_u32(smh);
    int tid = threadIdx.x, lane = tid & 31, w = tid >> 5;
    int gid = lane >> 2, tig = lane & 3;
    int wm0 = (w & 3) * 32, wn0 = (w >> 2) * 64;
    int m0 = blockIdx.y * 128, n0 = blockIdx.x * 128;
    int l8 = lane & 7;
    int aRowOff = ((lane >> 3) & 1) * 8 + l8, aColOff = (lane >> 4) * 8;
    int bRowOff = (lane >> 4) * 8 + l8,      bColOff = ((lane >> 3) & 1) * 8;

    float c[2][8][4];
#pragma unroll
    for (int i = 0; i < 2; i++)
#pragma unroll
        for (int j = 0; j < 8; j++)
#pragma unroll
            for (int e = 0; e < 4; e++) c[i][j][e] = 0.0f;

    const __half* abase[4];
#pragma unroll
    for (int i = 0; i < 4; i++) {
        int qd = tid + i * 256;
        int row = qd >> 3;
        int mg = m0 + row;
        int b = mg >> 10, pi = mg & 1023;
        int ii = pi >> 5, jj = pi & 31;
        abase[i] = xh + ((size_t)(b * 3) * 512 + ii * 16) * 512 + jj * 16;
    }

    auto load = [&](int ch, int s) {
        int k0 = ch * 64;
#pragma unroll
        for (int i = 0; i < 4; i++) {
            int qd = tid + i * 256;
            int row = qd >> 3, c8 = qd & 7;
            int k = k0 + c8 * 8;
            int cc = k >> 8, rr = (k >> 4) & 15, qq = k & 15;
            cp16(sbase + (uint32_t)(s * 9216 + row * 72 + c8 * 8) * 2,
                 abase[i] + (size_t)cc * 262144 + rr * 512 + qq, 16);
        }
#pragma unroll
        for (int i = 0; i < 4; i++) {
            int qd = tid + i * 256;
            int row = qd >> 3, c8 = qd & 7;
            cp16(sbase + (uint32_t)(27648 + s * 9216 + row * 72 + c8 * 8) * 2,
                 cwh + (size_t)(n0 + row) * PK + k0 + c8 * 8, 16);
        }
        CP_COMMIT;
    };

    load(0, 0);
    load(1, 1);
    for (int ch = 0; ch < 12; ch++) {
        int s = ch % 3;
        if (ch + 1 < 12) { CP_WAIT1; } else { CP_WAIT0; }
        __syncthreads();
        if (ch + 2 < 12) load(ch + 2, (ch + 2) % 3);
        uint32_t aBase = sbase + (uint32_t)(s * 9216) * 2;
        uint32_t bBase = sbase + (uint32_t)(27648 + s * 9216) * 2;
#pragma unroll
        for (int ks = 0; ks < 4; ks++) {
            uint32_t a[2][4], b[8][2];
#pragma unroll
            for (int mt = 0; mt < 2; mt++)
                ldmx4(a[mt][0], a[mt][1], a[mt][2], a[mt][3],
                      aBase + (uint32_t)((wm0 + mt * 16 + aRowOff) * 72
                                         + ks * 16 + aColOff) * 2);
#pragma unroll
            for (int np = 0; np < 4; np++)
                ldmx4(b[2*np][0], b[2*np][1], b[2*np+1][0], b[2*np+1][1],
                      bBase + (uint32_t)((wn0 + np * 16 + bRowOff) * 72
                                         + ks * 16 + bColOff) * 2);
#pragma unroll
            for (int mt = 0; mt < 2; mt++)
#pragma unroll
                for (int nt = 0; nt < 8; nt++)
                    mma16(c[mt][nt], a[mt], b[nt][0], b[nt][1]);
        }
    }

#pragma unroll
    for (int mt = 0; mt < 2; mt++) {
#pragma unroll
        for (int h2 = 0; h2 < 2; h2++) {
            int mg = m0 + wm0 + mt * 16 + gid + h2 * 8;
            int b = mg >> 10, pi = mg & 1023;
            __half* hp = h + (size_t)(b * SS + 1 + pi) * HH;
            const float* pp = pos + (size_t)(1 + pi) * HH;
#pragma unroll
            for (int nt = 0; nt < 8; nt++) {
                int col = n0 + wn0 + nt * 8 + tig * 2;
                float v0 = c[mt][nt][h2 * 2]     + cb[col]     + pp[col];
                float v1 = c[mt][nt][h2 * 2 + 1] + cb[col + 1] + pp[col + 1];
                *(__half2*)(hp + col) = __floats2half2_rn(v0, v1);
            }
        }
    }
}

// ------------------------- flash attention (fp16, 3-stage) -------------------
#define FA_SMEM (6*9216*2)
#define FA_VOFF 27648
#define NCHK 9

__global__ void __launch_bounds__(256)
flash_attn(const __half* __restrict__ qkv, __half* __restrict__ out)
{
    extern __shared__ __align__(16) __half smh[];
    uint32_t sbase = smem_u32(smh);
    int tid = threadIdx.x, lane = tid & 31, w = tid >> 5;
    int gid = lane >> 2, tig = lane & 3;
    int bh = blockIdx.y, bi = bh / NHH, hd = bh % NHH;
    int m0 = blockIdx.x * 128;
    int wm0 = w * 16;
    int l8 = lane & 7;
    int kRowOff = (lane >> 4) * 8 + l8, kColOff = ((lane >> 3) & 1) * 8;
    int lrow2 = lane & 15;
    int lrow = ((lane >> 3) & 1) * 8 + l8;
    int lcol = (lane >> 4) * 8;

    for (int r = tid; r < 384; r += 256) {
        int s = r >> 7, row = r & 127;
        uint32_t* vp = (uint32_t*)(smh + FA_VOFF + s * 9216 + row * 72 + 64);
        vp[0] = 0x00003C00u; vp[1] = 0u; vp[2] = 0u; vp[3] = 0u;
    }

    const float QS = 0.18033688011112042f;
    uint32_t qa[4][4];
    {
        int r0 = m0 + wm0 + gid, r1 = r0 + 8;
        const __half* q0 = qkv + (size_t)(bi * SS + (r0 < SS ? r0 : 0)) * QKVN + hd * 64;
        const __half* q1 = qkv + (size_t)(bi * SS + (r1 < SS ? r1 : 0)) * QKVN + hd * 64;
        float z0 = (r0 < SS) ? QS : 0.0f;
        float z1 = (r1 < SS) ? QS : 0.0f;
#pragma unroll
        for (int ks = 0; ks < 4; ks++) {
            __half2 t;
            t = __floats2half2_rn(__half2float(q0[ks*16 + tig*2]) * z0,
                                  __half2float(q0[ks*16 + tig*2 + 1]) * z0);
            qa[ks][0] = *(uint32_t*)&t;
            t = __floats2half2_rn(__half2float(q1[ks*16 + tig*2]) * z1,
                                  __half2float(q1[ks*16 + tig*2 + 1]) * z1);
            qa[ks][1] = *(uint32_t*)&t;
            t = __floats2half2_rn(__half2float(q0[ks*16 + 8 + tig*2]) * z0,
                                  __half2float(q0[ks*16 + 8 + tig*2 + 1]) * z0);
            qa[ks][2] = *(uint32_t*)&t;
            t = __floats2half2_rn(__half2float(q1[ks*16 + 8 + tig*2]) * z1,
                                  __half2float(q1[ks*16 + 8 + tig*2 + 1]) * z1);
            qa[ks][3] = *(uint32_t*)&t;
        }
    }

    float o[8][4];
#pragma unroll
    for (int i = 0; i < 8; i++)
#pragma unroll
        for (int e = 0; e < 4; e++) o[i][e] = 0.0f;
    float ol[4] = {0.0f, 0.0f, 0.0f, 0.0f};
    float m_run[2] = {-1e30f, -1e30f};

    auto loadKV = [&](int c, int s) {
        int jb = c * 128;
#pragma unroll
        for (int i = 0; i < 4; i++) {
            int qd = tid + i * 256;
            int row = qd >> 3, c8 = qd & 7;
            int j = jb + row;
            const __half* src = qkv + (size_t)(bi * SS + (j < SS ? j : 0)) * QKVN
                              + 384 + hd * 64 + c8 * 8;
            cp16(sbase + (uint32_t)(s * 9216 + row * 72 + c8 * 8) * 2, src,
                 (j < SS) ? 16 : 0);
        }
#pragma unroll
        for (int i = 0; i < 4; i++) {
            int qd = tid + i * 256;
            int row = qd >> 3, c8 = qd & 7;
            int j = jb + row;
            const __half* src = qkv + (size_t)(bi * SS + (j < SS ? j : 0)) * QKVN
                              + 768 + hd * 64 + c8 * 8;
            cp16(sbase + (uint32_t)(FA_VOFF + s * 9216 + row * 72 + c8 * 8) * 2, src,
                 (j < SS) ? 16 : 0);
        }
        CP_COMMIT;
    };

    loadKV(0, 0);
    loadKV(1, 1);

    for (int c = 0; c < NCHK - 1; c++) {
        int s = c % 3;
        CP_WAIT1;
        __syncthreads();
        if (c + 2 < NCHK) loadKV(c + 2, (c + 2) % 3);
        uint32_t kBase = sbase + (uint32_t)(s * 9216) * 2;
        uint32_t vbase = sbase + (uint32_t)(FA_VOFF + s * 9216) * 2;

        float sc[16][4];
#pragma unroll
        for (int i = 0; i < 16; i++)
#pragma unroll
            for (int e = 0; e < 4; e++) sc[i][e] = 0.0f;
#pragma unroll
        for (int ks = 0; ks < 4; ks++) {
#pragma unroll
            for (int np = 0; np < 8; np++) {
                uint32_t r0, r1, r2, r3;
                ldmx4(r0, r1, r2, r3,
                      kBase + (uint32_t)((np * 16 + kRowOff) * 72
                                         + ks * 16 + kColOff) * 2);
                mma16(sc[2*np],     qa[ks], r0, r1);
                mma16(sc[2*np + 1], qa[ks], r2, r3);
            }
        }

#pragma unroll
        for (int h2 = 0; h2 < 2; h2++) {
            float mx = -1e30f;
#pragma unroll
            for (int nt = 0; nt < 16; nt++)
                mx = fmaxf(mx, fmaxf(sc[nt][h2 * 2], sc[nt][h2 * 2 + 1]));
            mx = fmaxf(mx, __shfl_xor_sync(0xffffffffu, mx, 1));
            mx = fmaxf(mx, __shfl_xor_sync(0xffffffffu, mx, 2));
            float mnew = fmaxf(m_run[h2], mx);
            float corr = exp2f(m_run[h2] - mnew);
            m_run[h2] = mnew;
#pragma unroll
            for (int ng = 0; ng < 8; ng++) {
                o[ng][h2 * 2] *= corr;
                o[ng][h2 * 2 + 1] *= corr;
            }
            ol[h2 * 2] *= corr;
            ol[h2 * 2 + 1] *= corr;
        }

        float m0f = m_run[0], m1f = m_run[1];
#pragma unroll
        for (int ks = 0; ks < 8; ks++) {
            uint32_t pa[4];
            __half2 t;
            t = __floats2half2_rn(sc[2*ks][0] - m0f, sc[2*ks][1] - m0f);
            pa[0] = h2ex2(*(uint32_t*)&t);
            t = __floats2half2_rn(sc[2*ks][2] - m1f, sc[2*ks][3] - m1f);
            pa[1] = h2ex2(*(uint32_t*)&t);
            t = __floats2half2_rn(sc[2*ks+1][0] - m0f, sc[2*ks+1][1] - m0f);
            pa[2] = h2ex2(*(uint32_t*)&t);
            t = __floats2half2_rn(sc[2*ks+1][2] - m1f, sc[2*ks+1][3] - m1f);
            pa[3] = h2ex2(*(uint32_t*)&t);
#pragma unroll
            for (int np = 0; np < 4; np++) {
                uint32_t r0, r1, r2, r3;
                uint32_t addr = vbase
                    + (uint32_t)((ks * 16 + lrow) * 72 + np * 16 + lcol) * 2;
                ldmx4t(r0, r1, r2, r3, addr);
                mma16(o[np * 2],     pa, r0, r1);
                mma16(o[np * 2 + 1], pa, r2, r3);
            }
            uint32_t v0, v1;
            ldmx2t(v0, v1, vbase + (uint32_t)((ks * 16 + lrow2) * 72 + 64) * 2);
            mma16(ol, pa, v0, v1);
        }
    }

    // ---- tail chunk (c = 8): only key 1024 (col 0) valid ----
    {
        CP_WAIT0;
        __syncthreads();
        const int s = (NCHK - 1) % 3;   // 2
        uint32_t kBase = sbase + (uint32_t)(s * 9216) * 2;
        uint32_t vbase = sbase + (uint32_t)(FA_VOFF + s * 9216) * 2;

        float tsc[2][4];
#pragma unroll
        for (int i = 0; i < 2; i++)
#pragma unroll
            for (int e = 0; e < 4; e++) tsc[i][e] = 0.0f;
#pragma unroll
        for (int ks = 0; ks < 4; ks++) {
            uint32_t r0, r1, r2, r3;
            ldmx4(r0, r1, r2, r3,
                  kBase + (uint32_t)(kRowOff * 72 + ks * 16 + kColOff) * 2);
            mma16(tsc[0], qa[ks], r0, r1);
            mma16(tsc[1], qa[ks], r2, r3);
        }
#pragma unroll
        for (int nt = 0; nt < 2; nt++)
#pragma unroll
            for (int e = 0; e < 4; e++) {
                int col = nt * 8 + tig * 2 + (e & 1);
                if (col != 0) tsc[nt][e] = -1e30f;
            }
#pragma unroll
        for (int h2 = 0; h2 < 2; h2++) {
            float mx = fmaxf(fmaxf(tsc[0][h2 * 2], tsc[0][h2 * 2 + 1]),
                             fmaxf(tsc[1][h2 * 2], tsc[1][h2 * 2 + 1]));
            mx = fmaxf(mx, __shfl_xor_sync(0xffffffffu, mx, 1));
            mx = fmaxf(mx, __shfl_xor_sync(0xffffffffu, mx, 2));
            float mnew = fmaxf(m_run[h2], mx);
            float corr = exp2f(m_run[h2] - mnew);
            m_run[h2] = mnew;
#pragma unroll
            for (int ng = 0; ng < 8; ng++) {
                o[ng][h2 * 2] *= corr;
                o[ng][h2 * 2 + 1] *= corr;
            }
            ol[h2 * 2] *= corr;
            ol[h2 * 2 + 1] *= corr;
        }
        float m0f = m_run[0], m1f = m_run[1];
        uint32_t pa[4];
        __half2 t;
        t = __floats2half2_rn(tsc[0][0] - m0f, tsc[0][1] - m0f);
        pa[0] = h2ex2(*(uint32_t*)&t);
        t = __floats2half2_rn(tsc[0][2] - m1f, tsc[0][3] - m1f);
        pa[1] = h2ex2(*(uint32_t*)&t);
        t = __floats2half2_rn(tsc[1][0] - m0f, tsc[1][1] - m0f);
        pa[2] = h2ex2(*(uint32_t*)&t);
        t = __floats2half2_rn(tsc[1][2] - m1f, tsc[1][3] - m1f);
        pa[3] = h2ex2(*(uint32_t*)&t);
#pragma unroll
        for (int np = 0; np < 4; np++) {
            uint32_t r0, r1, r2, r3;
            ldmx4t(r0, r1, r2, r3,
                   vbase + (uint32_t)(lrow * 72 + np * 16 + lcol) * 2);
            mma16(o[np * 2],     pa, r0, r1);
            mma16(o[np * 2 + 1], pa, r2, r3);
        }
        uint32_t v0, v1;
        ldmx2t(v0, v1, vbase + (uint32_t)(lrow2 * 72 + 64) * 2);
        mma16(ol, pa, v0, v1);
    }

#pragma unroll
    for (int h2 = 0; h2 < 2; h2++) {
        int i = m0 + wm0 + gid + h2 * 8;
        float lv = __shfl_sync(0xffffffffu, ol[h2 * 2], lane & ~3);
        if (i >= SS) continue;
        float invl = 1.0f / lv;
        __half* op = out + (size_t)(bi * SS + i) * HH + hd * 64;
#pragma unroll
        for (int ng = 0; ng < 8; ng++) {
            int d = ng * 8 + tig * 2;
            *(__half2*)(op + d) = __floats2half2_rn(o[ng][h2 * 2] * invl,
                                                    o[ng][h2 * 2 + 1] * invl);
        }
    }
}

// -------------------------- weight prep -------------------------------------
__global__ void transcvt(const float* __restrict__ in, __half* __restrict__ out,
                         int K, int N, size_t outLayerStride, int rowOff)
{
    __shared__ float tile[32][33];
    int l = blockIdx.z;
    int k0 = blockIdx.y * 32, n0 = blockIdx.x * 32;
    const float* ip = in + (size_t)l * K * N;
    __half* op = out + (size_t)l * outLayerStride + (size_t)rowOff * K;
    int tx = threadIdx.x, ty = threadIdx.y;
#pragma unroll
    for (int i = 0; i < 32; i += 8)
        tile[ty + i][tx] = ip[(size_t)(k0 + ty + i) * N + n0 + tx];
    __syncthreads();
#pragma unroll
    for (int i = 0; i < 32; i += 8)
        op[(size_t)(n0 + ty + i) * K + k0 + tx] = __float2half(tile[tx][ty + i]);
}

__global__ void cvt_half4(const float* __restrict__ in, __half* __restrict__ out,
                          int n4)
{
    int i = blockIdx.x * 256 + threadIdx.x;
    if (i >= n4) return;
    float4 v = ((const float4*)in)[i];
    __half2 lo = __floats2half2_rn(v.x, v.y);
    __half2 hi = __floats2half2_rn(v.z, v.w);
    ((__half2*)out)[i * 2]     = lo;
    ((__half2*)out)[i * 2 + 1] = hi;
}

__global__ void pack_qkv_b(const float* __restrict__ bq,
                           const float* __restrict__ bk,
                           const float* __restrict__ bv,
                           float* __restrict__ out)
{
    int idx = blockIdx.x * 256 + threadIdx.x;
    if (idx >= LL * QKVN) return;
    int n = idx % QKVN;
    int l = idx / QKVN;
    const float* src = (n < HH) ? bq : (n < 2 * HH) ? bk : bv;
    out[idx] = src[l * HH + n % HH];
}

__global__ void cls_pos_kernel(const float* __restrict__ cls,
                               const float* __restrict__ pos,
                               __half* __restrict__ h)
{
    int t = blockIdx.x * 256 + threadIdx.x;
    if (t < BB * HH) {
        int b = t / HH, o = t % HH;
        h[(size_t)(b * SS) * HH + o] = __float2half(cls[o] + pos[o]);
    }
}

// --------------------------- LayerNorm (vectorized, fp32 math) ---------------
__global__ void ln_kernel(const __half* __restrict__ in,
                          const float* __restrict__ w,
                          const float* __restrict__ b,
                          __half* __restrict__ out)
{
    int row = blockIdx.x;
    const __half2* p = (const __half2*)(in + (size_t)row * HH);
    int t = threadIdx.x;            // 192 threads = 6 warps
    float2 v = __half22float2(p[t]);

    __shared__ float sh[6];
    float s = v.x + v.y;
#pragma unroll
    for (int o = 16; o; o >>= 1) s += __shfl_xor_sync(0xffffffffu, s, o);
    if ((t & 31) == 0) sh[t >> 5] = s;
    __syncthreads();
    float mu = (sh[0] + sh[1] + sh[2] + sh[3] + sh[4] + sh[5]) * (1.0f / 384.0f);
    __syncthreads();

    float d0 = v.x - mu, d1 = v.y - mu;
    float sq = d0 * d0 + d1 * d1;
#pragma unroll
    for (int o = 16; o; o >>= 1) sq += __shfl_xor_sync(0xffffffffu, sq, o);
    if ((t & 31) == 0) sh[t >> 5] = sq;
    __syncthreads();
    float var = (sh[0] + sh[1] + sh[2] + sh[3] + sh[4] + sh[5]) * (1.0f / 384.0f);
    float inv = rsqrtf(var + 1e-5f);

    float2 wv = ((const float2*)w)[t];
    float2 bv = ((const float2*)b)[t];
    __half2* q = (__half2*)(out + (size_t)row * HH);
    q[t] = __floats2half2_rn(d0 * inv * wv.x + bv.x, d1 * inv * wv.y + bv.y);
}

// ------------------------------- classifier ---------------------------------
__global__ void classifier_kernel(const __half* __restrict__ h,
                                  const float* __restrict__ wc,
                                  const float* __restrict__ bc,
                                  float* __restrict__ out)
{
    int t = blockIdx.x * 256 + threadIdx.x;
    if (t >= BB * NCC) return;
    int b = t / NCC, n = t % NCC;
    const __half* hp = h + (size_t)(b * SS) * HH;
    float acc = 0.0f;
    for (int k = 0; k < HH; k++) acc += __half2float(hp[k]) * wc[(size_t)k * NCC + n];
    out[t] = acc + bc[n];
}

// ------------------------------- host side ----------------------------------
extern "C" void kernel_launch(void* const* d_in, const int* in_sizes, int n_in,
                              void* d_out, int out_size)
{
    const float* x    = (const float*)d_in[0];
    const float* cw   = (const float*)d_in[1];
    const float* cb   = (const float*)d_in[2];
    const float* cls  = (const float*)d_in[3];
    const float* pos  = (const float*)d_in[4];
    const float* ln1w = (const float*)d_in[5];
    const float* ln1b = (const float*)d_in[6];
    const float* wq   = (const float*)d_in[7];
    const float* bq   = (const float*)d_in[8];
    const float* wk   = (const float*)d_in[9];
    const float* bk   = (const float*)d_in[10];
    const float* wv   = (const float*)d_in[11];
    const float* bv   = (const float*)d_in[12];
    const float* wo   = (const float*)d_in[13];
    const float* bo   = (const float*)d_in[14];
    const float* ln2w = (const float*)d_in[15];
    const float* ln2b = (const float*)d_in[16];
    const float* w1   = (const float*)d_in[17];
    const float* b1   = (const float*)d_in[18];
    const float* w2   = (const float*)d_in[19];
    const float* b2   = (const float*)d_in[20];
    const float* wc   = (const float*)d_in[21];
    const float* bc   = (const float*)d_in[22];

    __half *h, *hn, *qkv, *attn, *mlp, *xh, *cwh;
    __half *wqkv, *wot, *w1t, *w2t; float *bqkv;
    cudaGetSymbolAddress((void**)&h,    g_h);
    cudaGetSymbolAddress((void**)&hn,   g_hn);
    cudaGetSymbolAddress((void**)&qkv,  g_qkv);
    cudaGetSymbolAddress((void**)&attn, g_attn);
    cudaGetSymbolAddress((void**)&mlp,  g_mlp);
    cudaGetSymbolAddress((void**)&xh,   g_xh);
    cudaGetSymbolAddress((void**)&cwh,  g_cwh);
    cudaGetSymbolAddress((void**)&wqkv, g_wqkv);
    cudaGetSymbolAddress((void**)&bqkv, g_bqkv);
    cudaGetSymbolAddress((void**)&wot,  g_wot);
    cudaGetSymbolAddress((void**)&w1t,  g_w1t);
    cudaGetSymbolAddress((void**)&w2t,  g_w2t);

    // weight/input prep
    {
        dim3 tb(32, 8);
        transcvt<<<dim3(HH/32, HH/32, LL), tb>>>(wq, wqkv, HH, HH, (size_t)QKVN*HH, 0);
        transcvt<<<dim3(HH/32, HH/32, LL), tb>>>(wk, wqkv, HH, HH, (size_t)QKVN*HH, HH);
        transcvt<<<dim3(HH/32, HH/32, LL), tb>>>(wv, wqkv, HH, HH, (size_t)QKVN*HH, 2*HH);
        transcvt<<<dim3(HH/32, HH/32, LL), tb>>>(wo, wot, HH, HH, (size_t)HH*HH, 0);
        transcvt<<<dim3(II/32, HH/32, LL), tb>>>(w1, w1t, HH, II, (size_t)II*HH, 0);
        transcvt<<<dim3(HH/32, II/32, LL), tb>>>(w2, w2t, II, HH, (size_t)HH*II, 0);
        pack_qkv_b<<<(LL*QKVN + 255)/256, 256>>>(bq, bk, bv, bqkv);
        int nx4 = (BB*3*512*512)/4;
        cvt_half4<<<(nx4 + 255)/256, 256>>>(x, xh, nx4);
        int nw4 = (HH*PK)/4;
        cvt_half4<<<(nw4 + 255)/256, 256>>>(cw, cwh, nw4);
    }

    cudaFuncSetAttribute((const void*)mma_gemm<0>, cudaFuncAttributeMaxDynamicSharedMemorySize, DG_SMEM);
    cudaFuncSetAttribute((const void*)mma_gemm<1>, cudaFuncAttributeMaxDynamicSharedMemorySize, DG_SMEM);
    cudaFuncSetAttribute((const void*)mma_gemm<2>, cudaFuncAttributeMaxDynamicSharedMemorySize, DG_SMEM);
    cudaFuncSetAttribute((const void*)patch_mma, cudaFuncAttributeMaxDynamicSharedMemorySize, DG_SMEM_P);
    cudaFuncSetAttribute((const void*)flash_attn, cudaFuncAttributeMaxDynamicSharedMemorySize, FA_SMEM);

    patch_mma<<<dim3(HH/128, MPATCH/128), 256, DG_SMEM_P>>>(xh, cwh, cb, pos, h);
    cls_pos_kernel<<<(BB * HH + 255) / 256, 256>>>(cls, pos, h);

    int mt = (MTOK + 127) / 128;                 // 129
    dim3 gQKV(QKVN / 128, mt);                   // (9, 129)
    dim3 g384(HH / 128, mt);                     // (3, 129)
    dim3 g1536(II / 128, mt);                    // (12, 129)
    dim3 gFA((SS + 127) / 128, BB * NHH);        // (9, 96)

    for (int l = 0; l < LL; l++) {
        ln_kernel<<<MTOK, 192>>>(h, ln1w + l * HH, ln1b + l * HH, hn);
        mma_gemm<0><<<gQKV, 256, DG_SMEM>>>(hn, wqkv + (size_t)l * QKVN * HH,
                                            bqkv + l * QKVN, qkv, MTOK, QKVN, HH);
        flash_attn<<<gFA, 256, FA_SMEM>>>(qkv, attn);
        mma_gemm<1><<<g384, 256, DG_SMEM>>>(attn, wot + (size_t)l * HH * HH,
                                            bo + l * HH, h, MTOK, HH, HH);
        ln_kernel<<<MTOK, 192>>>(h, ln2w + l * HH, ln2b + l * HH, hn);
        mma_gemm<2><<<g1536, 256, DG_SMEM>>>(hn, w1t + (size_t)l * II * HH,
                                             b1 + l * II, mlp, MTOK, II, HH);
        mma_gemm<1><<<g384, 256, DG_SMEM>>>(mlp, w2t + (size_t)l * HH * II,
                                            b2 + l * HH, h, MTOK, HH, II);
    }

    classifier_kernel<<<(BB * NCC + 255) / 256, 256>>>(h, wc, bc, (float*)d_out);
}

// round 16
// speedup vs baseline: 1.1082x; 1.0736x over previous
#include <cuda_runtime.h>
#include <cuda_fp16.h>
#include <math.h>
#include <stdint.h>

#define BB 16
#define SS 1025
#define HH 384
#define NHH 6
#define LL 12
#define II 1536
#define NCC 1000
#define MTOK (BB*SS)       // 16400
#define NPATCH 1024
#define MPATCH (BB*NPATCH) // 16384
#define QKVN 1152          // 3*HH
#define PK 768             // patch K = 3*16*16

// ---------------- scratch (__device__ globals; allocation-free rule) -------
__device__ __align__(256) __half g_h[MTOK*HH];          // fp16 residual stream
__device__ __align__(256) __half g_hn[MTOK*HH];
__device__ __align__(256) __half g_qkv[(size_t)MTOK*QKVN];
__device__ __align__(256) __half g_attn[MTOK*HH];
__device__ __align__(256) __half g_mlp[MTOK*II];
__device__ __align__(256) __half g_xh[(size_t)BB*3*512*512];
__device__ __align__(256) __half g_cwh[HH*PK];
// fp16 weights, pre-transposed to [L][N][K]
__device__ __align__(256) __half g_wqkv[(size_t)LL*QKVN*HH];
__device__ __align__(256) float  g_bqkv[LL*QKVN];
__device__ __align__(256) __half g_wot[LL*HH*HH];
__device__ __align__(256) __half g_w1t[(size_t)LL*II*HH];
__device__ __align__(256) __half g_w2t[(size_t)LL*HH*II];

// ---------------------------- helpers ---------------------------------------
__device__ __forceinline__ uint32_t smem_u32(const void* p) {
    uint32_t a;
    asm("{ .reg .u64 t; cvta.to.shared.u64 t, %1; cvt.u32.u64 %0, t; }"
        : "=r"(a) : "l"(p));
    return a;
}

__device__ __forceinline__ void cp16(uint32_t dst, const void* src, int nbytes) {
    asm volatile("cp.async.cg.shared.global [%0], [%1], 16, %2;"
                 :: "r"(dst), "l"(src), "r"(nbytes) : "memory");
}
#define CP_COMMIT asm volatile("cp.async.commit_group;" ::: "memory")
#define CP_WAIT0  asm volatile("cp.async.wait_group 0;" ::: "memory")
#define CP_WAIT1  asm volatile("cp.async.wait_group 1;" ::: "memory")

__device__ __forceinline__ void mma16(float* c, const uint32_t* a,
                                      uint32_t b0, uint32_t b1) {
    asm volatile("mma.sync.aligned.m16n8k16.row.col.f32.f16.f16.f32 "
        "{%0,%1,%2,%3}, {%4,%5,%6,%7}, {%8,%9}, {%0,%1,%2,%3};"
        : "+f"(c[0]), "+f"(c[1]), "+f"(c[2]), "+f"(c[3])
        : "r"(a[0]), "r"(a[1]), "r"(a[2]), "r"(a[3]), "r"(b0), "r"(b1));
}

__device__ __forceinline__ void ldmx4(uint32_t& r0, uint32_t& r1,
                                      uint32_t& r2, uint32_t& r3, uint32_t addr) {
    asm volatile("ldmatrix.sync.aligned.m8n8.x4.shared.b16 {%0,%1,%2,%3}, [%4];"
        : "=r"(r0), "=r"(r1), "=r"(r2), "=r"(r3) : "r"(addr));
}

__device__ __forceinline__ void ldmx4t(uint32_t& r0, uint32_t& r1,
                                       uint32_t& r2, uint32_t& r3, uint32_t addr) {
    asm volatile("ldmatrix.sync.aligned.m8n8.x4.trans.shared.b16 {%0,%1,%2,%3}, [%4];"
        : "=r"(r0), "=r"(r1), "=r"(r2), "=r"(r3) : "r"(addr));
}

__device__ __forceinline__ void ldmx2t(uint32_t& r0, uint32_t& r1, uint32_t addr) {
    asm volatile("ldmatrix.sync.aligned.m8n8.x2.trans.shared.b16 {%0,%1}, [%2];"
        : "=r"(r0), "=r"(r1) : "r"(addr));
}

__device__ __forceinline__ uint32_t h2ex2(uint32_t x) {
    uint32_t r;
    asm("ex2.approx.f16x2 %0, %1;" : "=r"(r) : "r"(x));
    return r;
}

__device__ __forceinline__ float gelu_f(float u) {
    float a = -1.5957691216057308f * (u + 0.044715f * u * u * u);
    float e = __expf(fminf(a, 80.0f));
    float th = (1.0f - e) / (1.0f + e);
    return 0.5f * u * (1.0f + th);
}

// ------------------------- dense mma GEMM (fp16) -----------------------------
// C[M,N] = A[M,K] @ W^T (W stored [N][K]) + bias. All outputs fp16.
// EPI 0: bias; 1: bias + residual (C += old, fp32 math); 2: bias + gelu
// Block 128x128, 256 thr (8 warps: 4m x 2n), warp 32x64, K-chunk 64, 3 stages.
// All epilogues staged through smem for coalesced 16B global accesses.
#define DG_SMEM (6*9216*2)

template <int EPI>
__global__ void __launch_bounds__(256)
mma_gemm(const __half* __restrict__ A, const __half* __restrict__ Bw,
         const float* __restrict__ bias, __half* __restrict__ C,
         int M, int N, int K)
{
    extern __shared__ __align__(16) __half smh[];
    uint32_t sbase = smem_u32(smh);
    int tid = threadIdx.x, lane = tid & 31, w = tid >> 5;
    int gid = lane >> 2, tig = lane & 3;
    int wm0 = (w & 3) * 32, wn0 = (w >> 2) * 64;
    int m0 = blockIdx.y * 128, n0 = blockIdx.x * 128;
    int l8 = lane & 7;
    int aRowOff = ((lane >> 3) & 1) * 8 + l8, aColOff = (lane >> 4) * 8;
    int bRowOff = (lane >> 4) * 8 + l8,      bColOff = ((lane >> 3) & 1) * 8;

    float c[2][8][4];
#pragma unroll
    for (int i = 0; i < 2; i++)
#pragma unroll
        for (int j = 0; j < 8; j++)
#pragma unroll
            for (int e = 0; e < 4; e++) c[i][j][e] = 0.0f;

    int nch = K >> 6;
    auto load = [&](int ch, int s) {
        int k0 = ch * 64;
#pragma unroll
        for (int i = 0; i < 4; i++) {
            int qd = tid + i * 256;
            int row = qd >> 3, c8 = qd & 7;
            int mg = (m0 + row < M) ? m0 + row : M - 1;
            cp16(sbase + (uint32_t)(s * 9216 + row * 72 + c8 * 8) * 2,
                 A + (size_t)mg * K + k0 + c8 * 8, (m0 + row < M) ? 16 : 0);
        }
#pragma unroll
        for (int i = 0; i < 4; i++) {
            int qd = tid + i * 256;
            int row = qd >> 3, c8 = qd & 7;
            cp16(sbase + (uint32_t)(27648 + s * 9216 + row * 72 + c8 * 8) * 2,
                 Bw + (size_t)(n0 + row) * K + k0 + c8 * 8, 16);
        }
        CP_COMMIT;
    };

    load(0, 0);
    if (nch > 1) load(1, 1);
    for (int ch = 0; ch < nch; ch++) {
        int s = ch % 3;
        if (ch + 1 < nch) { CP_WAIT1; } else { CP_WAIT0; }
        __syncthreads();
        if (ch + 2 < nch) load(ch + 2, (ch + 2) % 3);
        uint32_t aBase = sbase + (uint32_t)(s * 9216) * 2;
        uint32_t bBase = sbase + (uint32_t)(27648 + s * 9216) * 2;
#pragma unroll
        for (int ks = 0; ks < 4; ks++) {
            uint32_t a[2][4], b[8][2];
#pragma unroll
            for (int mt = 0; mt < 2; mt++)
                ldmx4(a[mt][0], a[mt][1], a[mt][2], a[mt][3],
                      aBase + (uint32_t)((wm0 + mt * 16 + aRowOff) * 72
                                         + ks * 16 + aColOff) * 2);
#pragma unroll
            for (int np = 0; np < 4; np++)
                ldmx4(b[2*np][0], b[2*np][1], b[2*np+1][0], b[2*np+1][1],
                      bBase + (uint32_t)((wn0 + np * 16 + bRowOff) * 72
                                         + ks * 16 + bColOff) * 2);
#pragma unroll
            for (int mt = 0; mt < 2; mt++)
#pragma unroll
                for (int nt = 0; nt < 8; nt++)
                    mma16(c[mt][nt], a[mt], b[nt][0], b[nt][1]);
        }
    }

    if (EPI == 1) {
        // residual path: coalesced prefetch of old C, smem add, coalesced store
        __syncthreads();
#pragma unroll
        for (int i = 0; i < 8; i++) {
            int idx = tid + i * 256;
            int row = idx >> 4, chk = idx & 15;
            int mg = m0 + row;
            cp16(sbase + (uint32_t)(row * 136 + chk * 8) * 2,
                 C + (size_t)(mg < M ? mg : M - 1) * N + n0 + chk * 8,
                 (mg < M) ? 16 : 0);
        }
        CP_COMMIT; CP_WAIT0;
        __syncthreads();
#pragma unroll
        for (int mt = 0; mt < 2; mt++) {
#pragma unroll
            for (int nt = 0; nt < 8; nt++) {
                int colL = wn0 + nt * 8 + tig * 2;
                float b0 = bias[n0 + colL], b1 = bias[n0 + colL + 1];
#pragma unroll
                for (int h2 = 0; h2 < 2; h2++) {
                    int rl = wm0 + mt * 16 + gid + h2 * 8;
                    float2 of = __half22float2(*(__half2*)(smh + rl * 136 + colL));
                    float v0 = c[mt][nt][h2 * 2] + b0 + of.x;
                    float v1 = c[mt][nt][h2 * 2 + 1] + b1 + of.y;
                    *(__half2*)(smh + 17408 + rl * 136 + colL)
                        = __floats2half2_rn(v0, v1);
                }
            }
        }
        __syncthreads();
#pragma unroll
        for (int i = 0; i < 8; i++) {
            int idx = tid + i * 256;
            int row = idx >> 4, chk = idx & 15;
            int mg = m0 + row;
            if (mg < M) {
                uint4 v = *(const uint4*)(smh + 17408 + row * 136 + chk * 8);
                *(uint4*)(C + (size_t)mg * N + n0 + chk * 8) = v;
            }
        }
    } else {
        // pure-store path: stage through smem, coalesced 16B global stores
        __syncthreads();
#pragma unroll
        for (int mt = 0; mt < 2; mt++) {
#pragma unroll
            for (int nt = 0; nt < 8; nt++) {
                int colL = wn0 + nt * 8 + tig * 2;
                float b0 = bias[n0 + colL], b1 = bias[n0 + colL + 1];
#pragma unroll
                for (int h2 = 0; h2 < 2; h2++) {
                    int rl = wm0 + mt * 16 + gid + h2 * 8;
                    float v0 = c[mt][nt][h2 * 2] + b0;
                    float v1 = c[mt][nt][h2 * 2 + 1] + b1;
                    if (EPI == 2) { v0 = gelu_f(v0); v1 = gelu_f(v1); }
                    *(__half2*)(smh + rl * 136 + colL) = __floats2half2_rn(v0, v1);
                }
            }
        }
        __syncthreads();
#pragma unroll
        for (int i = 0; i < 8; i++) {
            int idx = tid + i * 256;
            int row = idx >> 4, chk = idx & 15;
            int mg = m0 + row;
            if (mg < M) {
                uint4 v = *(const uint4*)(smh + row * 136 + chk * 8);
                *(uint4*)(C + (size_t)mg * N + n0 + chk * 8) = v;
            }
        }
    }
}

// ------------------------- patch embed GEMM (fp16 mma) -----------------------
#define DG_SMEM_P ((3*9216 + 3*128*72)*2)

__global__ void __launch_bounds__(256)
patch_mma(const __half* __restrict__ xh, const __half* __restrict__ cwh,
          const float* __restrict__ cb, const float* __restrict__ pos,
          __half* __restrict__ h)
{
    extern __shared__ __align__(16) __half smh[];
    uint32_t sbase = smem_u32(smh);
    int tid = threadIdx.x, lane = tid & 31, w = tid >> 5;
    int gid = lane >> 2, tig = lane & 3;
    int wm0 = (w & 3) * 32, wn0 = (w >> 2) * 64;
    int m0 = blockIdx.y * 128, n0 = blockIdx.x * 128;
    int l8 = lane & 7;
    int aRowOff = ((lane >> 3) & 1) * 8 + l8, aColOff = (lane >> 4) * 8;
    int bRowOff = (lane >> 4) * 8 + l8,      bColOff = ((lane >> 3) & 1) * 8;

    float c[2][8][4];
#pragma unroll
    for (int i = 0; i < 2; i++)
#pragma unroll
        for (int j = 0; j < 8; j++)
#pragma unroll
            for (int e = 0; e < 4; e++) c[i][j][e] = 0.0f;

    const __half* abase[4];
#pragma unroll
    for (int i = 0; i < 4; i++) {
        int qd = tid + i * 256;
        int row = qd >> 3;
        int mg = m0 + row;
        int b = mg >> 10, pi = mg & 1023;
        int ii = pi >> 5, jj = pi & 31;
        abase[i] = xh + ((size_t)(b * 3) * 512 + ii * 16) * 512 + jj * 16;
    }

    auto load = [&](int ch, int s) {
        int k0 = ch * 64;
#pragma unroll
        for (int i = 0; i < 4; i++) {
            int qd = tid + i * 256;
            int row = qd >> 3, c8 = qd & 7;
            int k = k0 + c8 * 8;
            int cc = k >> 8, rr = (k >> 4) & 15, qq = k & 15;
            cp16(sbase + (uint32_t)(s * 9216 + row * 72 + c8 * 8) * 2,
                 abase[i] + (size_t)cc * 262144 + rr * 512 + qq, 16);
        }
#pragma unroll
        for (int i = 0; i < 4; i++) {
            int qd = tid + i * 256;
            int row = qd >> 3, c8 = qd & 7;
            cp16(sbase + (uint32_t)(27648 + s * 9216 + row * 72 + c8 * 8) * 2,
                 cwh + (size_t)(n0 + row) * PK + k0 + c8 * 8, 16);
        }
        CP_COMMIT;
    };

    load(0, 0);
    load(1, 1);
    for (int ch = 0; ch < 12; ch++) {
        int s = ch % 3;
        if (ch + 1 < 12) { CP_WAIT1; } else { CP_WAIT0; }
        __syncthreads();
        if (ch + 2 < 12) load(ch + 2, (ch + 2) % 3);
        uint32_t aBase = sbase + (uint32_t)(s * 9216) * 2;
        uint32_t bBase = sbase + (uint32_t)(27648 + s * 9216) * 2;
#pragma unroll
        for (int ks = 0; ks < 4; ks++) {
            uint32_t a[2][4], b[8][2];
#pragma unroll
            for (int mt = 0; mt < 2; mt++)
                ldmx4(a[mt][0], a[mt][1], a[mt][2], a[mt][3],
                      aBase + (uint32_t)((wm0 + mt * 16 + aRowOff) * 72
                                         + ks * 16 + aColOff) * 2);
#pragma unroll
            for (int np = 0; np < 4; np++)
                ldmx4(b[2*np][0], b[2*np][1], b[2*np+1][0], b[2*np+1][1],
                      bBase + (uint32_t)((wn0 + np * 16 + bRowOff) * 72
                                         + ks * 16 + bColOff) * 2);
#pragma unroll
            for (int mt = 0; mt < 2; mt++)
#pragma unroll
                for (int nt = 0; nt < 8; nt++)
                    mma16(c[mt][nt], a[mt], b[nt][0], b[nt][1]);
        }
    }

#pragma unroll
    for (int mt = 0; mt < 2; mt++) {
#pragma unroll
        for (int h2 = 0; h2 < 2; h2++) {
            int mg = m0 + wm0 + mt * 16 + gid + h2 * 8;
            int b = mg >> 10, pi = mg & 1023;
            __half* hp = h + (size_t)(b * SS + 1 + pi) * HH;
            const float* pp = pos + (size_t)(1 + pi) * HH;
#pragma unroll
            for (int nt = 0; nt < 8; nt++) {
                int col = n0 + wn0 + nt * 8 + tig * 2;
                float v0 = c[mt][nt][h2 * 2]     + cb[col]     + pp[col];
                float v1 = c[mt][nt][h2 * 2 + 1] + cb[col + 1] + pp[col + 1];
                *(__half2*)(hp + col) = __floats2half2_rn(v0, v1);
            }
        }
    }
}

// ------------------------- flash attention (fp16, 3-stage) -------------------
#define FA_SMEM (6*9216*2)
#define FA_VOFF 27648
#define NCHK 9

__global__ void __launch_bounds__(256)
flash_attn(const __half* __restrict__ qkv, __half* __restrict__ out)
{
    extern __shared__ __align__(16) __half smh[];
    uint32_t sbase = smem_u32(smh);
    int tid = threadIdx.x, lane = tid & 31, w = tid >> 5;
    int gid = lane >> 2, tig = lane & 3;
    int bh = blockIdx.y, bi = bh / NHH, hd = bh % NHH;
    int m0 = blockIdx.x * 128;
    int wm0 = w * 16;
    int l8 = lane & 7;
    int kRowOff = (lane >> 4) * 8 + l8, kColOff = ((lane >> 3) & 1) * 8;
    int lrow2 = lane & 15;
    int lrow = ((lane >> 3) & 1) * 8 + l8;
    int lcol = (lane >> 4) * 8;

    for (int r = tid; r < 384; r += 256) {
        int s = r >> 7, row = r & 127;
        uint32_t* vp = (uint32_t*)(smh + FA_VOFF + s * 9216 + row * 72 + 64);
        vp[0] = 0x00003C00u; vp[1] = 0u; vp[2] = 0u; vp[3] = 0u;
    }

    const float QS = 0.18033688011112042f;
    uint32_t qa[4][4];
    {
        int r0 = m0 + wm0 + gid, r1 = r0 + 8;
        const __half* q0 = qkv + (size_t)(bi * SS + (r0 < SS ? r0 : 0)) * QKVN + hd * 64;
        const __half* q1 = qkv + (size_t)(bi * SS + (r1 < SS ? r1 : 0)) * QKVN + hd * 64;
        float z0 = (r0 < SS) ? QS : 0.0f;
        float z1 = (r1 < SS) ? QS : 0.0f;
#pragma unroll
        for (int ks = 0; ks < 4; ks++) {
            __half2 t;
            t = __floats2half2_rn(__half2float(q0[ks*16 + tig*2]) * z0,
                                  __half2float(q0[ks*16 + tig*2 + 1]) * z0);
            qa[ks][0] = *(uint32_t*)&t;
            t = __floats2half2_rn(__half2float(q1[ks*16 + tig*2]) * z1,
                                  __half2float(q1[ks*16 + tig*2 + 1]) * z1);
            qa[ks][1] = *(uint32_t*)&t;
            t = __floats2half2_rn(__half2float(q0[ks*16 + 8 + tig*2]) * z0,
                                  __half2float(q0[ks*16 + 8 + tig*2 + 1]) * z0);
            qa[ks][2] = *(uint32_t*)&t;
            t = __floats2half2_rn(__half2float(q1[ks*16 + 8 + tig*2]) * z1,
                                  __half2float(q1[ks*16 + 8 + tig*2 + 1]) * z1);
            qa[ks][3] = *(uint32_t*)&t;
        }
    }

    float o[8][4];
#pragma unroll
    for (int i = 0; i < 8; i++)
#pragma unroll
        for (int e = 0; e < 4; e++) o[i][e] = 0.0f;
    float ol[4] = {0.0f, 0.0f, 0.0f, 0.0f};
    float m_run[2] = {-1e30f, -1e30f};

    auto loadKV = [&](int c, int s) {
        int jb = c * 128;
#pragma unroll
        for (int i = 0; i < 4; i++) {
            int qd = tid + i * 256;
            int row = qd >> 3, c8 = qd & 7;
            int j = jb + row;
            const __half* src = qkv + (size_t)(bi * SS + (j < SS ? j : 0)) * QKVN
                              + 384 + hd * 64 + c8 * 8;
            cp16(sbase + (uint32_t)(s * 9216 + row * 72 + c8 * 8) * 2, src,
                 (j < SS) ? 16 : 0);
        }
#pragma unroll
        for (int i = 0; i < 4; i++) {
            int qd = tid + i * 256;
            int row = qd >> 3, c8 = qd & 7;
            int j = jb + row;
            const __half* src = qkv + (size_t)(bi * SS + (j < SS ? j : 0)) * QKVN
                              + 768 + hd * 64 + c8 * 8;
            cp16(sbase + (uint32_t)(FA_VOFF + s * 9216 + row * 72 + c8 * 8) * 2, src,
                 (j < SS) ? 16 : 0);
        }
        CP_COMMIT;
    };

    loadKV(0, 0);
    loadKV(1, 1);

    for (int c = 0; c < NCHK - 1; c++) {
        int s = c % 3;
        CP_WAIT1;
        __syncthreads();
        if (c + 2 < NCHK) loadKV(c + 2, (c + 2) % 3);
        uint32_t kBase = sbase + (uint32_t)(s * 9216) * 2;
        uint32_t vbase = sbase + (uint32_t)(FA_VOFF + s * 9216) * 2;

        float sc[16][4];
#pragma unroll
        for (int i = 0; i < 16; i++)
#pragma unroll
            for (int e = 0; e < 4; e++) sc[i][e] = 0.0f;
#pragma unroll
        for (int ks = 0; ks < 4; ks++) {
#pragma unroll
            for (int np = 0; np < 8; np++) {
                uint32_t r0, r1, r2, r3;
                ldmx4(r0, r1, r2, r3,
                      kBase + (uint32_t)((np * 16 + kRowOff) * 72
                                         + ks * 16 + kColOff) * 2);
                mma16(sc[2*np],     qa[ks], r0, r1);
                mma16(sc[2*np + 1], qa[ks], r2, r3);
            }
        }

#pragma unroll
        for (int h2 = 0; h2 < 2; h2++) {
            float mx = -1e30f;
#pragma unroll
            for (int nt = 0; nt < 16; nt++)
                mx = fmaxf(mx, fmaxf(sc[nt][h2 * 2], sc[nt][h2 * 2 + 1]));
            mx = fmaxf(mx, __shfl_xor_sync(0xffffffffu, mx, 1));
            mx = fmaxf(mx, __shfl_xor_sync(0xffffffffu, mx, 2));
            float mnew = fmaxf(m_run[h2], mx);
            float corr = exp2f(m_run[h2] - mnew);
            m_run[h2] = mnew;
#pragma unroll
            for (int ng = 0; ng < 8; ng++) {
                o[ng][h2 * 2] *= corr;
                o[ng][h2 * 2 + 1] *= corr;
            }
            ol[h2 * 2] *= corr;
            ol[h2 * 2 + 1] *= corr;
        }

        float m0f = m_run[0], m1f = m_run[1];
#pragma unroll
        for (int ks = 0; ks < 8; ks++) {
            uint32_t pa[4];
            __half2 t;
            t = __floats2half2_rn(sc[2*ks][0] - m0f, sc[2*ks][1] - m0f);
            pa[0] = h2ex2(*(uint32_t*)&t);
            t = __floats2half2_rn(sc[2*ks][2] - m1f, sc[2*ks][3] - m1f);
            pa[1] = h2ex2(*(uint32_t*)&t);
            t = __floats2half2_rn(sc[2*ks+1][0] - m0f, sc[2*ks+1][1] - m0f);
            pa[2] = h2ex2(*(uint32_t*)&t);
            t = __floats2half2_rn(sc[2*ks+1][2] - m1f, sc[2*ks+1][3] - m1f);
            pa[3] = h2ex2(*(uint32_t*)&t);
#pragma unroll
            for (int np = 0; np < 4; np++) {
                uint32_t r0, r1, r2, r3;
                uint32_t addr = vbase
                    + (uint32_t)((ks * 16 + lrow) * 72 + np * 16 + lcol) * 2;
                ldmx4t(r0, r1, r2, r3, addr);
                mma16(o[np * 2],     pa, r0, r1);
                mma16(o[np * 2 + 1], pa, r2, r3);
            }
            uint32_t v0, v1;
            ldmx2t(v0, v1, vbase + (uint32_t)((ks * 16 + lrow2) * 72 + 64) * 2);
            mma16(ol, pa, v0, v1);
        }
    }

    // ---- tail chunk (c = 8): only key 1024 (col 0) valid ----
    {
        CP_WAIT0;
        __syncthreads();
        const int s = (NCHK - 1) % 3;   // 2
        uint32_t kBase = sbase + (uint32_t)(s * 9216) * 2;
        uint32_t vbase = sbase + (uint32_t)(FA_VOFF + s * 9216) * 2;

        float tsc[2][4];
#pragma unroll
        for (int i = 0; i < 2; i++)
#pragma unroll
            for (int e = 0; e < 4; e++) tsc[i][e] = 0.0f;
#pragma unroll
        for (int ks = 0; ks < 4; ks++) {
            uint32_t r0, r1, r2, r3;
            ldmx4(r0, r1, r2, r3,
                  kBase + (uint32_t)(kRowOff * 72 + ks * 16 + kColOff) * 2);
            mma16(tsc[0], qa[ks], r0, r1);
            mma16(tsc[1], qa[ks], r2, r3);
        }
#pragma unroll
        for (int nt = 0; nt < 2; nt++)
#pragma unroll
            for (int e = 0; e < 4; e++) {
                int col = nt * 8 + tig * 2 + (e & 1);
                if (col != 0) tsc[nt][e] = -1e30f;
            }
#pragma unroll
        for (int h2 = 0; h2 < 2; h2++) {
            float mx = fmaxf(fmaxf(tsc[0][h2 * 2], tsc[0][h2 * 2 + 1]),
                             fmaxf(tsc[1][h2 * 2], tsc[1][h2 * 2 + 1]));
            mx = fmaxf(mx, __shfl_xor_sync(0xffffffffu, mx, 1));
            mx = fmaxf(mx, __shfl_xor_sync(0xffffffffu, mx, 2));
            float mnew = fmaxf(m_run[h2], mx);
            float corr = exp2f(m_run[h2] - mnew);
            m_run[h2] = mnew;
#pragma unroll
            for (int ng = 0; ng < 8; ng++) {
                o[ng][h2 * 2] *= corr;
                o[ng][h2 * 2 + 1] *= corr;
            }
            ol[h2 * 2] *= corr;
            ol[h2 * 2 + 1] *= corr;
        }
        float m0f = m_run[0], m1f = m_run[1];
        uint32_t pa[4];
        __half2 t;
        t = __floats2half2_rn(tsc[0][0] - m0f, tsc[0][1] - m0f);
        pa[0] = h2ex2(*(uint32_t*)&t);
        t = __floats2half2_rn(tsc[0][2] - m1f, tsc[0][3] - m1f);
        pa[1] = h2ex2(*(uint32_t*)&t);
        t = __floats2half2_rn(tsc[1][0] - m0f, tsc[1][1] - m0f);
        pa[2] = h2ex2(*(uint32_t*)&t);
        t = __floats2half2_rn(tsc[1][2] - m1f, tsc[1][3] - m1f);
        pa[3] = h2ex2(*(uint32_t*)&t);
#pragma unroll
        for (int np = 0; np < 4; np++) {
            uint32_t r0, r1, r2, r3;
            ldmx4t(r0, r1, r2, r3,
                   vbase + (uint32_t)(lrow * 72 + np * 16 + lcol) * 2);
            mma16(o[np * 2],     pa, r0, r1);
            mma16(o[np * 2 + 1], pa, r2, r3);
        }
        uint32_t v0, v1;
        ldmx2t(v0, v1, vbase + (uint32_t)(lrow2 * 72 + 64) * 2);
        mma16(ol, pa, v0, v1);
    }

#pragma unroll
    for (int h2 = 0; h2 < 2; h2++) {
        int i = m0 + wm0 + gid + h2 * 8;
        float lv = __shfl_sync(0xffffffffu, ol[h2 * 2], lane & ~3);
        if (i >= SS) continue;
        float invl = 1.0f / lv;
        __half* op = out + (size_t)(bi * SS + i) * HH + hd * 64;
#pragma unroll
        for (int ng = 0; ng < 8; ng++) {
            int d = ng * 8 + tig * 2;
            *(__half2*)(op + d) = __floats2half2_rn(o[ng][h2 * 2] * invl,
                                                    o[ng][h2 * 2 + 1] * invl);
        }
    }
}

// -------------------------- weight prep -------------------------------------
__global__ void transcvt(const float* __restrict__ in, __half* __restrict__ out,
                         int K, int N, size_t outLayerStride, int rowOff)
{
    __shared__ float tile[32][33];
    int l = blockIdx.z;
    int k0 = blockIdx.y * 32, n0 = blockIdx.x * 32;
    const float* ip = in + (size_t)l * K * N;
    __half* op = out + (size_t)l * outLayerStride + (size_t)rowOff * K;
    int tx = threadIdx.x, ty = threadIdx.y;
#pragma unroll
    for (int i = 0; i < 32; i += 8)
        tile[ty + i][tx] = ip[(size_t)(k0 + ty + i) * N + n0 + tx];
    __syncthreads();
#pragma unroll
    for (int i = 0; i < 32; i += 8)
        op[(size_t)(n0 + ty + i) * K + k0 + tx] = __float2half(tile[tx][ty + i]);
}

__global__ void cvt_half4(const float* __restrict__ in, __half* __restrict__ out,
                          int n4)
{
    int i = blockIdx.x * 256 + threadIdx.x;
    if (i >= n4) return;
    float4 v = ((const float4*)in)[i];
    __half2 lo = __floats2half2_rn(v.x, v.y);
    __half2 hi = __floats2half2_rn(v.z, v.w);
    ((__half2*)out)[i * 2]     = lo;
    ((__half2*)out)[i * 2 + 1] = hi;
}

__global__ void pack_qkv_b(const float* __restrict__ bq,
                           const float* __restrict__ bk,
                           const float* __restrict__ bv,
                           float* __restrict__ out)
{
    int idx = blockIdx.x * 256 + threadIdx.x;
    if (idx >= LL * QKVN) return;
    int n = idx % QKVN;
    int l = idx / QKVN;
    const float* src = (n < HH) ? bq : (n < 2 * HH) ? bk : bv;
    out[idx] = src[l * HH + n % HH];
}

__global__ void cls_pos_kernel(const float* __restrict__ cls,
                               const float* __restrict__ pos,
                               __half* __restrict__ h)
{
    int t = blockIdx.x * 256 + threadIdx.x;
    if (t < BB * HH) {
        int b = t / HH, o = t % HH;
        h[(size_t)(b * SS) * HH + o] = __float2half(cls[o] + pos[o]);
    }
}

// --------------------------- LayerNorm (vectorized, fp32 math) ---------------
__global__ void ln_kernel(const __half* __restrict__ in,
                          const float* __restrict__ w,
                          const float* __restrict__ b,
                          __half* __restrict__ out)
{
    int row = blockIdx.x;
    const __half2* p = (const __half2*)(in + (size_t)row * HH);
    int t = threadIdx.x;            // 192 threads = 6 warps
    float2 v = __half22float2(p[t]);

    __shared__ float sh[6];
    float s = v.x + v.y;
#pragma unroll
    for (int o = 16; o; o >>= 1) s += __shfl_xor_sync(0xffffffffu, s, o);
    if ((t & 31) == 0) sh[t >> 5] = s;
    __syncthreads();
    float mu = (sh[0] + sh[1] + sh[2] + sh[3] + sh[4] + sh[5]) * (1.0f / 384.0f);
    __syncthreads();

    float d0 = v.x - mu, d1 = v.y - mu;
    float sq = d0 * d0 + d1 * d1;
#pragma unroll
    for (int o = 16; o; o >>= 1) sq += __shfl_xor_sync(0xffffffffu, sq, o);
    if ((t & 31) == 0) sh[t >> 5] = sq;
    __syncthreads();
    float var = (sh[0] + sh[1] + sh[2] + sh[3] + sh[4] + sh[5]) * (1.0f / 384.0f);
    float inv = rsqrtf(var + 1e-5f);

    float2 wv = ((const float2*)w)[t];
    float2 bv = ((const float2*)b)[t];
    __half2* q = (__half2*)(out + (size_t)row * HH);
    q[t] = __floats2half2_rn(d0 * inv * wv.x + bv.x, d1 * inv * wv.y + bv.y);
}

// ------------------------------- classifier ---------------------------------
__global__ void classifier_kernel(const __half* __restrict__ h,
                                  const float* __restrict__ wc,
                                  const float* __restrict__ bc,
                                  float* __restrict__ out)
{
    int t = blockIdx.x * 256 + threadIdx.x;
    if (t >= BB * NCC) return;
    int b = t / NCC, n = t % NCC;
    const __half* hp = h + (size_t)(b * SS) * HH;
    float acc = 0.0f;
    for (int k = 0; k < HH; k++) acc += __half2float(hp[k]) * wc[(size_t)k * NCC + n];
    out[t] = acc + bc[n];
}

// ------------------------------- host side ----------------------------------
extern "C" void kernel_launch(void* const* d_in, const int* in_sizes, int n_in,
                              void* d_out, int out_size)
{
    const float* x    = (const float*)d_in[0];
    const float* cw   = (const float*)d_in[1];
    const float* cb   = (const float*)d_in[2];
    const float* cls  = (const float*)d_in[3];
    const float* pos  = (const float*)d_in[4];
    const float* ln1w = (const float*)d_in[5];
    const float* ln1b = (const float*)d_in[6];
    const float* wq   = (const float*)d_in[7];
    const float* bq   = (const float*)d_in[8];
    const float* wk   = (const float*)d_in[9];
    const float* bk   = (const float*)d_in[10];
    const float* wv   = (const float*)d_in[11];
    const float* bv   = (const float*)d_in[12];
    const float* wo   = (const float*)d_in[13];
    const float* bo   = (const float*)d_in[14];
    const float* ln2w = (const float*)d_in[15];
    const float* ln2b = (const float*)d_in[16];
    const float* w1   = (const float*)d_in[17];
    const float* b1   = (const float*)d_in[18];
    const float* w2   = (const float*)d_in[19];
    const float* b2   = (const float*)d_in[20];
    const float* wc   = (const float*)d_in[21];
    const float* bc   = (const float*)d_in[22];

    __half *h, *hn, *qkv, *attn, *mlp, *xh, *cwh;
    __half *wqkv, *wot, *w1t, *w2t; float *bqkv;
    cudaGetSymbolAddress((void**)&h,    g_h);
    cudaGetSymbolAddress((void**)&hn,   g_hn);
    cudaGetSymbolAddress((void**)&qkv,  g_qkv);
    cudaGetSymbolAddress((void**)&attn, g_attn);
    cudaGetSymbolAddress((void**)&mlp,  g_mlp);
    cudaGetSymbolAddress((void**)&xh,   g_xh);
    cudaGetSymbolAddress((void**)&cwh,  g_cwh);
    cudaGetSymbolAddress((void**)&wqkv, g_wqkv);
    cudaGetSymbolAddress((void**)&bqkv, g_bqkv);
    cudaGetSymbolAddress((void**)&wot,  g_wot);
    cudaGetSymbolAddress((void**)&w1t,  g_w1t);
    cudaGetSymbolAddress((void**)&w2t,  g_w2t);

    // weight/input prep
    {
        dim3 tb(32, 8);
        transcvt<<<dim3(HH/32, HH/32, LL), tb>>>(wq, wqkv, HH, HH, (size_t)QKVN*HH, 0);
        transcvt<<<dim3(HH/32, HH/32, LL), tb>>>(wk, wqkv, HH, HH, (size_t)QKVN*HH, HH);
        transcvt<<<dim3(HH/32, HH/32, LL), tb>>>(wv, wqkv, HH, HH, (size_t)QKVN*HH, 2*HH);
        transcvt<<<dim3(HH/32, HH/32, LL), tb>>>(wo, wot, HH, HH, (size_t)HH*HH, 0);
        transcvt<<<dim3(II/32, HH/32, LL), tb>>>(w1, w1t, HH, II, (size_t)II*HH, 0);
        transcvt<<<dim3(HH/32, II/32, LL), tb>>>(w2, w2t, II, HH, (size_t)HH*II, 0);
        pack_qkv_b<<<(LL*QKVN + 255)/256, 256>>>(bq, bk, bv, bqkv);
        int nx4 = (BB*3*512*512)/4;
        cvt_half4<<<(nx4 + 255)/256, 256>>>(x, xh, nx4);
        int nw4 = (HH*PK)/4;
        cvt_half4<<<(nw4 + 255)/256, 256>>>(cw, cwh, nw4);
    }

    cudaFuncSetAttribute((const void*)mma_gemm<0>, cudaFuncAttributeMaxDynamicSharedMemorySize, DG_SMEM);
    cudaFuncSetAttribute((const void*)mma_gemm<1>, cudaFuncAttributeMaxDynamicSharedMemorySize, DG_SMEM);
    cudaFuncSetAttribute((const void*)mma_gemm<2>, cudaFuncAttributeMaxDynamicSharedMemorySize, DG_SMEM);
    cudaFuncSetAttribute((const void*)patch_mma, cudaFuncAttributeMaxDynamicSharedMemorySize, DG_SMEM_P);
    cudaFuncSetAttribute((const void*)flash_attn, cudaFuncAttributeMaxDynamicSharedMemorySize, FA_SMEM);

    patch_mma<<<dim3(HH/128, MPATCH/128), 256, DG_SMEM_P>>>(xh, cwh, cb, pos, h);
    cls_pos_kernel<<<(BB * HH + 255) / 256, 256>>>(cls, pos, h);

    int mt = (MTOK + 127) / 128;                 // 129
    dim3 gQKV(QKVN / 128, mt);                   // (9, 129)
    dim3 g384(HH / 128, mt);                     // (3, 129)
    dim3 g1536(II / 128, mt);                    // (12, 129)
    dim3 gFA((SS + 127) / 128, BB * NHH);        // (9, 96)

    for (int l = 0; l < LL; l++) {
        ln_kernel<<<MTOK, 192>>>(h, ln1w + l * HH, ln1b + l * HH, hn);
        mma_gemm<0><<<gQKV, 256, DG_SMEM>>>(hn, wqkv + (size_t)l * QKVN * HH,
                                            bqkv + l * QKVN, qkv, MTOK, QKVN, HH);
        flash_attn<<<gFA, 256, FA_SMEM>>>(qkv, attn);
        mma_gemm<1><<<g384, 256, DG_SMEM>>>(attn, wot + (size_t)l * HH * HH,
                                            bo + l * HH, h, MTOK, HH, HH);
        ln_kernel<<<MTOK, 192>>>(h, ln2w + l * HH, ln2b + l * HH, hn);
        mma_gemm<2><<<g1536, 256, DG_SMEM>>>(hn, w1t + (size_t)l * II * HH,
                                             b1 + l * II, mlp, MTOK, II, HH);
        mma_gemm<1><<<g384, 256, DG_SMEM>>>(mlp, w2t + (size_t)l * HH * II,
                                            b2 + l * HH, h, MTOK, HH, II);
    }

    classifier_kernel<<<(BB * NCC + 255) / 256, 256>>>(h, wc, bc, (float*)d_out);
}